// round 9
// baseline (speedup 1.0000x reference)
#include <cuda_runtime.h>
#include <cuda_bf16.h>
#include <math.h>
#include <stdint.h>

// Problem constants (fixed by setup_inputs)
#define BB   4
#define CC   64
#define OO   64
#define HH   128
#define WW   128
#define HWSZ (HH * WW)

// Padded pair-image dims: rows/cols -1..130 (offset +1), pair (x-1, x)
#define PDIM 132
#define PSZ  (PDIM * PDIM)

// Scratch: offset-conv output; split weights; padded pair image of x
#define WPITCH 584
__device__ float g_om[BB * 27 * HWSZ];
__device__ unsigned short g_w2[2 * OO * WPITCH];
__device__ float2 g_x2[BB * CC * PSZ];      // 35.7 MB

typedef unsigned long long u64;

// ---- packed fp32x2 helpers (Blackwell FFMA2, used by K1) ----
__device__ __forceinline__ u64 dup2(float v) {
    u64 r; asm("mov.b64 %0, {%1, %1};" : "=l"(r) : "f"(v)); return r;
}
__device__ __forceinline__ void fma2(u64& d, u64 a, u64 b) {
    asm("fma.rn.f32x2 %0, %1, %2, %0;" : "+l"(d) : "l"(a), "l"(b));
}
__device__ __forceinline__ void unpack2(u64 v, float& lo, float& hi) {
    asm("mov.b64 {%0, %1}, %2;" : "=f"(lo), "=f"(hi) : "l"(v));
}

__device__ __forceinline__ uint32_t smem_u32(const void* p) {
    uint32_t a;
    asm("{ .reg .u64 t; cvta.to.shared.u64 t, %1; cvt.u32.u64 %0, t; }"
        : "=r"(a) : "l"(p));
    return a;
}
__device__ __forceinline__ void ldsm4(uint32_t* r, uint32_t addr) {
    asm volatile("ldmatrix.sync.aligned.m8n8.x4.shared.b16 {%0,%1,%2,%3}, [%4];"
        : "=r"(r[0]), "=r"(r[1]), "=r"(r[2]), "=r"(r[3]) : "r"(addr));
}
__device__ __forceinline__ void mma_bf16(float* d, const uint32_t* a, const uint32_t* b) {
    asm volatile(
        "mma.sync.aligned.m16n8k16.row.col.f32.bf16.bf16.f32 "
        "{%0,%1,%2,%3}, {%4,%5,%6,%7}, {%8,%9}, {%0,%1,%2,%3};"
        : "+f"(d[0]), "+f"(d[1]), "+f"(d[2]), "+f"(d[3])
        : "r"(a[0]), "r"(a[1]), "r"(a[2]), "r"(a[3]), "r"(b[0]), "r"(b[1]));
}

// ---------------------------------------------------------------------------
// Prep A: build padded pair image g_x2[b][c][ry][rx] = (x(ry-1,rx-2), x(ry-1,rx-1))
//   i.e. pair at rx covers x-values (rx-2, rx-1)?  -- see indexing below:
//   g_x2[..][ry][rx] = ( x(ry-1, rx-1-0? ) )  We define:
//   g_x2[ry][rx] = ( X(ry-1, rx-1), X(ry-1, rx) ), zero outside.
//   A sample with clamped x0c reads rx = x0c+1 -> pair (X(x0c), X(x0c+1)).
// ---------------------------------------------------------------------------
__global__ void prep_x_kernel(const float* __restrict__ x)
{
    int idx = blockIdx.x * 256 + threadIdx.x;
    const int total = BB * CC * PSZ;
    if (idx >= total) return;
    int rx = idx % PDIM;
    int t  = idx / PDIM;
    int ry = t % PDIM;
    int bc = t / PDIM;
    int yy  = ry - 1;
    int xx0 = rx - 1;
    const float* src = x + (size_t)bc * HWSZ;
    float v0 = 0.f, v1 = 0.f;
    if (yy >= 0 && yy < HH) {
        if (xx0 >= 0 && xx0 < WW)         v0 = src[yy * WW + xx0];
        if (xx0 + 1 >= 0 && xx0 + 1 < WW) v1 = src[yy * WW + xx0 + 1];
    }
    g_x2[idx] = make_float2(v0, v1);
}

// ---------------------------------------------------------------------------
// Prep B: split w_def into bf16 hi/lo, layout [o][k=tap*64+c], pitch 584.
// ---------------------------------------------------------------------------
__global__ void prep_w_kernel(const float* __restrict__ w_def)
{
    int o = blockIdx.x;
    int col = blockIdx.y * 128 + threadIdx.x;
    if (col >= WPITCH) return;
    unsigned short h = 0, l = 0;
    if (col < 576) {
        int tap = col >> 6, c = col & 63;
        float w = w_def[(o * CC + c) * 9 + tap];
        __nv_bfloat16 hb = __float2bfloat16(w);
        __nv_bfloat16 lb = __float2bfloat16(w - __bfloat162float(hb));
        h = __bfloat16_as_ushort(hb);
        l = __bfloat16_as_ushort(lb);
    }
    g_w2[o * WPITCH + col] = h;
    g_w2[OO * WPITCH + o * WPITCH + col] = l;
}

// ---------------------------------------------------------------------------
// Kernel 1: 3x3 conv producing 27 offset/mask channels (FFMA2, unchanged).
// ---------------------------------------------------------------------------
#define K1_W_FLOATS (576 * 32)
#define K1_F_FLOATS (CC * 4 * 136)
#define K1_SMEM_BYTES ((K1_W_FLOATS + K1_F_FLOATS) * 4)

__global__ __launch_bounds__(512, 1)
void offset_conv_kernel(const float* __restrict__ feat,
                        const float* __restrict__ w_off,
                        const float* __restrict__ b_off)
{
    extern __shared__ float smem[];
    float* w_s    = smem;
    float* feat_s = smem + K1_W_FLOATS;

    const int y0  = blockIdx.x * 2;
    const int b   = blockIdx.y;
    const int tid = threadIdx.x;

    for (int idx = tid; idx < K1_W_FLOATS; idx += 512) {
        int o = idx & 31;
        int k = idx >> 5;
        int c = k / 9;
        int r = k - c * 9;
        w_s[idx] = (o < 27) ? w_off[(o * CC + c) * 9 + r] : 0.f;
    }
    const float* fb = feat + (size_t)b * CC * HWSZ;
    for (int idx = tid; idx < K1_F_FLOATS; idx += 512) {
        int xx = idx % 136;
        int t  = idx / 136;
        int rr = t & 3;
        int c  = t >> 2;
        int yy = y0 - 1 + rr;
        int xg = xx - 1;
        float v = 0.f;
        if (xx < 132 && yy >= 0 && yy < HH && xg >= 0 && xg < WW)
            v = fb[(c * HH + yy) * WW + xg];
        feat_s[idx] = v;
    }
    __syncthreads();

    const int o0   = (tid >> 6) * 4;
    const int px0  = (tid & 63) * 4;
    const int rowo = px0 >> 7;
    const int xloc = px0 & 127;

    u64 acc2[2][4];
#pragma unroll
    for (int j = 0; j < 2; j++)
#pragma unroll
        for (int i = 0; i < 4; i++) acc2[j][i] = 0ULL;

    for (int c = 0; c < CC; c++) {
#pragma unroll
        for (int ky = 0; ky < 3; ky++) {
            const float* row = &feat_s[(c * 4 + rowo + ky) * 136 + xloc];
            float4 fa = *(const float4*)row;
            float2 fb2 = *(const float2*)(row + 4);
            float f[6] = {fa.x, fa.y, fa.z, fa.w, fb2.x, fb2.y};
            u64 fd[6];
#pragma unroll
            for (int t = 0; t < 6; t++) fd[t] = dup2(f[t]);
#pragma unroll
            for (int kx = 0; kx < 3; kx++) {
                const ulonglong2 wp =
                    *(const ulonglong2*)&w_s[((c * 9 + ky * 3 + kx) << 5) + o0];
#pragma unroll
                for (int i = 0; i < 4; i++) {
                    fma2(acc2[0][i], wp.x, fd[i + kx]);
                    fma2(acc2[1][i], wp.y, fd[i + kx]);
                }
            }
        }
    }

    const int yout = y0 + rowo;
#pragma unroll
    for (int jp = 0; jp < 2; jp++) {
        float vlo[4], vhi[4];
#pragma unroll
        for (int i = 0; i < 4; i++) unpack2(acc2[jp][i], vlo[i], vhi[i]);
        int oA = o0 + 2 * jp;
        int oB = oA + 1;
        if (oA < 27) {
            float bo = b_off[oA];
            float* op = &g_om[((b * 27 + oA) * HH + yout) * WW + xloc];
            *(float4*)op = make_float4(vlo[0] + bo, vlo[1] + bo, vlo[2] + bo, vlo[3] + bo);
        }
        if (oB < 27) {
            float bo = b_off[oB];
            float* op = &g_om[((b * 27 + oB) * HH + yout) * WW + xloc];
            *(float4*)op = make_float4(vhi[0] + bo, vhi[1] + bo, vhi[2] + bo, vhi[3] + bo);
        }
    }
}

// ---------------------------------------------------------------------------
// Kernel 2: deform-GEMM on tensor cores, mma.sync bf16 hi/lo split.
// Gathers use the padded pair image: 2 x LDG.64 per channel (rows y0, y0+1)
// instead of 4 x LDG.32 -> LSU stream halved.
// Double-buffered A tiles; per phase p: fill(p+1); mma(p); barrier.
// smem: Whi+Wlo (146KB) + 2 x (Ahi[256][40] + Alo) (80KB) = 231424 B.
// ---------------------------------------------------------------------------
#define SM_WHI 0
#define SM_WLO (OO * WPITCH * 2)                 // 74752
#define SM_A   (2 * OO * WPITCH * 2)             // 149504
#define A_HALF 20480                             // 256*80
#define A_BUF  (2 * A_HALF)                      // hi+lo per buffer
#define K2_SMEM (SM_A + 2 * A_BUF)               // 231424

__global__ __launch_bounds__(512, 1)
void deform_mma_kernel(const float* __restrict__ b_def,
                       float* __restrict__ out)
{
    extern __shared__ char smc[];
    const uint32_t sb = smem_u32(smc);

    const int y0  = blockIdx.x * 2;
    const int b   = blockIdx.y;
    const int tid = threadIdx.x;
    const int warp = tid >> 5;
    const int lane = tid & 31;

    // stage split weights (149504 B) into smem
    {
        const uint4* src = (const uint4*)g_w2;
        uint4* dst = (uint4*)smc;
        for (int i = tid; i < (2 * OO * WPITCH * 2) / 16; i += 512)
            dst[i] = src[i];
    }

    // fill identity: px = tid&255, channel group = (tid>>8)*16
    const int px    = tid & 255;
    const int chg   = (tid >> 8) * 16;
    const int yrow  = y0 + (px >> 7);
    const int gx    = px & 127;
    const float2* x2b = g_x2 + (size_t)b * CC * PSZ;
    const int ombase = (b * 27 * HH + yrow) * WW + gx;

    // mma identity
    const int px0 = warp * 16;

    float acc[8][4];
#pragma unroll
    for (int ob = 0; ob < 8; ob++)
#pragma unroll
        for (int i = 0; i < 4; i++) acc[ob][i] = 0.f;

    // precomputed ldmatrix lane addressing
    const uint32_t a_row  = px0 + (lane & 15);
    const uint32_t a_colb = (lane >> 4) * 16;
    const uint32_t aA = sb + SM_A + a_row * 80 + a_colb;
    const int bg  = lane >> 3;
    const int bl8 = lane & 7;
    const uint32_t b_row_off = ((bg >> 1) * 8 + bl8) * (WPITCH * 2);
    const uint32_t b_k8     = (bg & 1) * 16;     // byte offset for +8 k

    // per-tap sampling params (live across phases)
    float w00, w01, w10, w11;
    int   pofs;

    auto compute_params = [&](int tap) {
        float offx = g_om[ombase + tap * HWSZ];
        float offy = g_om[ombase + (9 + tap) * HWSZ];
        float mz   = g_om[ombase + (18 + tap) * HWSZ];
        float m    = 1.f / (1.f + __expf(-mz));
        float ys = (float)(yrow + tap / 3 - 1) + offy;
        float xs = (float)(gx + tap % 3 - 1) + offx;
        float y0f = floorf(ys), x0f = floorf(xs);
        float wy1 = ys - y0f,   wx1 = xs - x0f;
        float wy0 = 1.f - wy1,  wx0 = 1.f - wx1;
        int iy0 = (int)y0f, ix0 = (int)x0f;
        bool vy0 = (iy0 >= 0) && (iy0 < HH);
        bool vy1 = (iy0 + 1 >= 0) && (iy0 + 1 < HH);
        bool vx0 = (ix0 >= 0) && (ix0 < WW);
        bool vx1 = (ix0 + 1 >= 0) && (ix0 + 1 < WW);
        w00 = (vy0 && vx0) ? wy0 * wx0 * m : 0.f;
        w01 = (vy0 && vx1) ? wy0 * wx1 * m : 0.f;
        w10 = (vy1 && vx0) ? wy1 * wx0 * m : 0.f;
        w11 = (vy1 && vx1) ? wy1 * wx1 * m : 0.f;
        int yc = min(max(iy0, -1), HH);     // clamp into pad range
        int xc = min(max(ix0, -1), WW);
        pofs = (yc + 1) * PDIM + (xc + 1);  // pair at xc+1 covers (xc, xc+1)
    };

    // fill phase pn into buffer pn&1 (new tap params when entering even half)
    auto fill = [&](int pn) {
        const int tapn = pn >> 1;
        const int halfn = pn & 1;
        if (halfn == 0) compute_params(tapn);
        const int cbase = halfn * 32 + chg;
        const float2* xp0 = x2b + (size_t)cbase * PSZ + pofs;
        char* ahp = smc + SM_A + halfn * A_BUF + px * 80 + chg * 2;
        char* alp = ahp + A_HALF;
#pragma unroll
        for (int j = 0; j < 4; j++) {
            float v[4];
#pragma unroll
            for (int q = 0; q < 4; q++) {
                const float2* p = xp0 + (size_t)(4 * j + q) * PSZ;
                float2 ra = p[0];        // row y0: (x0, x0+1)
                float2 rb = p[PDIM];     // row y0+1
                v[q] = w00 * ra.x + w01 * ra.y + w10 * rb.x + w11 * rb.y;
            }
            unsigned short h[4], l[4];
#pragma unroll
            for (int q = 0; q < 4; q++) {
                __nv_bfloat16 hb = __float2bfloat16(v[q]);
                __nv_bfloat16 lb = __float2bfloat16(v[q] - __bfloat162float(hb));
                h[q] = __bfloat16_as_ushort(hb);
                l[q] = __bfloat16_as_ushort(lb);
            }
            uint2 hp, lp;
            hp.x = ((uint32_t)h[1] << 16) | h[0];
            hp.y = ((uint32_t)h[3] << 16) | h[2];
            lp.x = ((uint32_t)l[1] << 16) | l[0];
            lp.y = ((uint32_t)l[3] << 16) | l[2];
            *(uint2*)(ahp + 8 * j) = hp;
            *(uint2*)(alp + 8 * j) = lp;
        }
    };

    // prologue
    fill(0);
    __syncthreads();

    for (int p = 0; p < 18; p++) {
        // pipeline: fill next phase's buffer
        if (p < 17) fill(p + 1);

        // mma over phase p's 32-k chunk from buffer p&1
        const int tap  = p >> 1;
        const int half = p & 1;
        const uint32_t abase = aA + (uint32_t)(half * A_BUF);
#pragma unroll
        for (int ks = 0; ks < 2; ks++) {
            const int kglob = tap * 64 + half * 32 + ks * 16;
            uint32_t ah[4], al[4];
            ldsm4(ah, abase + ks * 32);
            ldsm4(al, abase + A_HALF + ks * 32);
            uint32_t bh[16], bl[16];
            const uint32_t bcol = kglob * 2 + b_k8;
#pragma unroll
            for (int obp = 0; obp < 4; obp++) {
                uint32_t roff = (uint32_t)(obp * 16) * (WPITCH * 2) + b_row_off + bcol;
                ldsm4(&bh[obp * 4], sb + SM_WHI + roff);
                ldsm4(&bl[obp * 4], sb + SM_WLO + roff);
            }
#pragma unroll
            for (int ob = 0; ob < 8; ob++) mma_bf16(acc[ob], ah, &bh[ob * 2]);
#pragma unroll
            for (int ob = 0; ob < 8; ob++) mma_bf16(acc[ob], ah, &bl[ob * 2]);
#pragma unroll
            for (int ob = 0; ob < 8; ob++) mma_bf16(acc[ob], al, &bh[ob * 2]);
        }
        __syncthreads();
    }

    // ---- epilogue: bias + relu ----
    {
        const int prow = px0 + (lane >> 2);
        const int row1 = y0 + (prow >> 7);
        const int x1   = prow & 127;
        const int prow2 = prow + 8;
        const int row2 = y0 + (prow2 >> 7);
        const int x2   = prow2 & 127;
#pragma unroll
        for (int ob = 0; ob < 8; ob++) {
            int o = ob * 8 + (lane & 3) * 2;
            float b0v = __ldg(b_def + o);
            float b1v = __ldg(b_def + o + 1);
            float* p1 = out + (((size_t)(b * OO + o) * HH + row1) * WW + x1);
            float* p2 = out + (((size_t)(b * OO + o) * HH + row2) * WW + x2);
            p1[0]    = fmaxf(acc[ob][0] + b0v, 0.f);
            p1[HWSZ] = fmaxf(acc[ob][1] + b1v, 0.f);
            p2[0]    = fmaxf(acc[ob][2] + b0v, 0.f);
            p2[HWSZ] = fmaxf(acc[ob][3] + b1v, 0.f);
        }
    }
}

// ---------------------------------------------------------------------------
extern "C" void kernel_launch(void* const* d_in, const int* in_sizes, int n_in,
                              void* d_out, int out_size)
{
    const float* x     = (const float*)d_in[0];
    const float* feat  = (const float*)d_in[1];
    const float* w_off = (const float*)d_in[2];
    const float* b_off = (const float*)d_in[3];
    const float* w_def = (const float*)d_in[4];
    const float* b_def = (const float*)d_in[5];
    float* out = (float*)d_out;

    cudaFuncSetAttribute(offset_conv_kernel,
                         cudaFuncAttributeMaxDynamicSharedMemorySize, K1_SMEM_BYTES);
    cudaFuncSetAttribute(deform_mma_kernel,
                         cudaFuncAttributeMaxDynamicSharedMemorySize, K2_SMEM);

    const int nx2 = BB * CC * PSZ;
    prep_x_kernel<<<(nx2 + 255) / 256, 256>>>(x);
    dim3 gridp(OO, 5);
    prep_w_kernel<<<gridp, 128>>>(w_def);
    dim3 grid1(HH / 2, BB);
    offset_conv_kernel<<<grid1, 512, K1_SMEM_BYTES>>>(feat, w_off, b_off);
    dim3 grid2(HH / 2, BB);
    deform_mma_kernel<<<grid2, 512, K2_SMEM>>>(b_def, out);
}

// round 10
// speedup vs baseline: 1.2943x; 1.2943x over previous
#include <cuda_runtime.h>
#include <cuda_bf16.h>
#include <math.h>
#include <stdint.h>

// Problem constants (fixed by setup_inputs)
#define BB   4
#define CC   64
#define OO   64
#define HH   128
#define WW   128
#define HWSZ (HH * WW)

// Scratch: offset-conv output; split weights (def: 64 o, off: 32 o padded)
#define WPITCH 584
#define NOFF   32
__device__ float g_om[BB * 27 * HWSZ];
__device__ unsigned short g_w2[2 * OO * WPITCH];     // w_def hi | lo
__device__ unsigned short g_w1[2 * NOFF * WPITCH];   // w_off hi | lo (o>=27 zero)

__device__ __forceinline__ uint32_t smem_u32(const void* p) {
    uint32_t a;
    asm("{ .reg .u64 t; cvta.to.shared.u64 t, %1; cvt.u32.u64 %0, t; }"
        : "=r"(a) : "l"(p));
    return a;
}
__device__ __forceinline__ void ldsm4(uint32_t* r, uint32_t addr) {
    asm volatile("ldmatrix.sync.aligned.m8n8.x4.shared.b16 {%0,%1,%2,%3}, [%4];"
        : "=r"(r[0]), "=r"(r[1]), "=r"(r[2]), "=r"(r[3]) : "r"(addr));
}
__device__ __forceinline__ void mma_bf16(float* d, const uint32_t* a, const uint32_t* b) {
    asm volatile(
        "mma.sync.aligned.m16n8k16.row.col.f32.bf16.bf16.f32 "
        "{%0,%1,%2,%3}, {%4,%5,%6,%7}, {%8,%9}, {%0,%1,%2,%3};"
        : "+f"(d[0]), "+f"(d[1]), "+f"(d[2]), "+f"(d[3])
        : "r"(a[0]), "r"(a[1]), "r"(a[2]), "r"(a[3]), "r"(b[0]), "r"(b[1]));
}
__device__ __forceinline__ void split_pack(const float* v, uint2& hp, uint2& lp) {
    unsigned short h[4], l[4];
#pragma unroll
    for (int q = 0; q < 4; q++) {
        __nv_bfloat16 hb = __float2bfloat16(v[q]);
        __nv_bfloat16 lb = __float2bfloat16(v[q] - __bfloat162float(hb));
        h[q] = __bfloat16_as_ushort(hb);
        l[q] = __bfloat16_as_ushort(lb);
    }
    hp.x = ((uint32_t)h[1] << 16) | h[0];
    hp.y = ((uint32_t)h[3] << 16) | h[2];
    lp.x = ((uint32_t)l[1] << 16) | l[0];
    lp.y = ((uint32_t)l[3] << 16) | l[2];
}

// ---------------------------------------------------------------------------
// Prep: split w_def (blocks 0..63) and w_off (blocks 64..95) into bf16 hi/lo,
// layout [o][k=tap*64+c], pitch 584.
// ---------------------------------------------------------------------------
__global__ void prep_w_kernel(const float* __restrict__ w_def,
                              const float* __restrict__ w_off)
{
    int ob  = blockIdx.x;
    int col = blockIdx.y * 128 + threadIdx.x;
    if (col >= WPITCH) return;
    float w = 0.f;
    if (col < 576) {
        int tap = col >> 6, c = col & 63;
        if (ob < OO) w = w_def[(ob * CC + c) * 9 + tap];
        else if (ob - OO < 27) w = w_off[((ob - OO) * CC + c) * 9 + tap];
    }
    __nv_bfloat16 hb = __float2bfloat16(w);
    __nv_bfloat16 lb = __float2bfloat16(w - __bfloat162float(hb));
    if (ob < OO) {
        g_w2[ob * WPITCH + col] = __bfloat16_as_ushort(hb);
        g_w2[OO * WPITCH + ob * WPITCH + col] = __bfloat16_as_ushort(lb);
    } else {
        int o = ob - OO;
        g_w1[o * WPITCH + col] = __bfloat16_as_ushort(hb);
        g_w1[NOFF * WPITCH + o * WPITCH + col] = __bfloat16_as_ushort(lb);
    }
}

// ---------------------------------------------------------------------------
// Kernel 1 (tensor-core): offset conv as im2col GEMM.
// One CTA per (b, 2 rows): om[27(pad32) o][256 px], K=576 (k=tap*64+c).
// A tile = shifted feat reads (coalesced). Same mma machinery as K2, N=32.
// smem: W (74752 B) + 2 x A buffers (81920 B) = 156672 B.
// ---------------------------------------------------------------------------
#define A_HALF 20480                             // 256*80
#define A_BUF  (2 * A_HALF)                      // hi+lo per buffer

#define K1_SMW  (2 * NOFF * WPITCH * 2)          // 74752
#define K1_SMA  K1_SMW
#define K1_SMEM (K1_SMA + 2 * A_BUF)             // 156672

__global__ __launch_bounds__(512, 1)
void offset_mma_kernel(const float* __restrict__ feat,
                       const float* __restrict__ b_off)
{
    extern __shared__ char smc[];
    const uint32_t sb = smem_u32(smc);

    const int y0  = blockIdx.x * 2;
    const int b   = blockIdx.y;
    const int tid = threadIdx.x;
    const int warp = tid >> 5;
    const int lane = tid & 31;

    // stage split w_off into smem
    {
        const uint4* src = (const uint4*)g_w1;
        uint4* dst = (uint4*)smc;
        for (int i = tid; i < K1_SMW / 16; i += 512)
            dst[i] = src[i];
    }

    const int px    = tid & 255;
    const int chg   = (tid >> 8) * 16;
    const int yrow  = y0 + (px >> 7);
    const int gx    = px & 127;
    const float* fb = feat + (size_t)b * CC * HWSZ;

    const int px0 = warp * 16;

    float acc[4][4];
#pragma unroll
    for (int ob = 0; ob < 4; ob++)
#pragma unroll
        for (int i = 0; i < 4; i++) acc[ob][i] = 0.f;

    const uint32_t a_row  = px0 + (lane & 15);
    const uint32_t a_colb = (lane >> 4) * 16;
    const uint32_t aA = sb + K1_SMA + a_row * 80 + a_colb;
    const int bg  = lane >> 3;
    const int bl8 = lane & 7;
    const uint32_t b_row_off = ((bg >> 1) * 8 + bl8) * (WPITCH * 2);
    const uint32_t b_k8     = (bg & 1) * 16;

    auto fill = [&](int pn) {
        const int tapn = pn >> 1;
        const int halfn = pn & 1;
        const int dy = tapn / 3 - 1, dx = tapn % 3 - 1;
        const int yy = yrow + dy, xx = gx + dx;
        const bool valid = (yy >= 0) && (yy < HH) && (xx >= 0) && (xx < WW);
        const int cbase = halfn * 32 + chg;
        const float* fp = fb + (size_t)cbase * HWSZ + yy * WW + xx;
        char* ahp = smc + K1_SMA + halfn * A_BUF + px * 80 + chg * 2;
        char* alp = ahp + A_HALF;
#pragma unroll
        for (int j = 0; j < 4; j++) {
            float v[4];
#pragma unroll
            for (int q = 0; q < 4; q++)
                v[q] = valid ? __ldg(fp + (size_t)(4 * j + q) * HWSZ) : 0.f;
            uint2 hp, lp;
            split_pack(v, hp, lp);
            *(uint2*)(ahp + 8 * j) = hp;
            *(uint2*)(alp + 8 * j) = lp;
        }
    };

    fill(0);
    __syncthreads();

    for (int p = 0; p < 18; p++) {
        if (p < 17) fill(p + 1);

        const int tap  = p >> 1;
        const int half = p & 1;
        const uint32_t abase = aA + (uint32_t)(half * A_BUF);
#pragma unroll
        for (int ks = 0; ks < 2; ks++) {
            const int kglob = tap * 64 + half * 32 + ks * 16;
            uint32_t ah[4], al[4];
            ldsm4(ah, abase + ks * 32);
            ldsm4(al, abase + A_HALF + ks * 32);
            uint32_t bh[8], bl[8];
            const uint32_t bcol = kglob * 2 + b_k8;
#pragma unroll
            for (int obp = 0; obp < 2; obp++) {
                uint32_t roff = (uint32_t)(obp * 16) * (WPITCH * 2) + b_row_off + bcol;
                ldsm4(&bh[obp * 4], sb + roff);
                ldsm4(&bl[obp * 4], sb + (uint32_t)(NOFF * WPITCH * 2) + roff);
            }
#pragma unroll
            for (int ob = 0; ob < 4; ob++) mma_bf16(acc[ob], ah, &bh[ob * 2]);
#pragma unroll
            for (int ob = 0; ob < 4; ob++) mma_bf16(acc[ob], ah, &bl[ob * 2]);
#pragma unroll
            for (int ob = 0; ob < 4; ob++) mma_bf16(acc[ob], al, &bh[ob * 2]);
        }
        __syncthreads();
    }

    // epilogue: bias, store to g_om (no relu); only o < 27
    {
        const int prow = px0 + (lane >> 2);
        const int row1 = y0 + (prow >> 7);
        const int x1   = prow & 127;
        const int prow2 = prow + 8;
        const int row2 = y0 + (prow2 >> 7);
        const int x2   = prow2 & 127;
#pragma unroll
        for (int ob = 0; ob < 4; ob++) {
            int o = ob * 8 + (lane & 3) * 2;
            if (o < 27) {
                float bv = __ldg(b_off + o);
                float* p1 = &g_om[((b * 27 + o) * HH + row1) * WW + x1];
                float* p2 = &g_om[((b * 27 + o) * HH + row2) * WW + x2];
                p1[0] = acc[ob][0] + bv;
                p2[0] = acc[ob][2] + bv;
            }
            if (o + 1 < 27) {
                float bv = __ldg(b_off + o + 1);
                float* p1 = &g_om[((b * 27 + o + 1) * HH + row1) * WW + x1];
                float* p2 = &g_om[((b * 27 + o + 1) * HH + row2) * WW + x2];
                p1[0] = acc[ob][1] + bv;
                p2[0] = acc[ob][3] + bv;
            }
        }
    }
}

// ---------------------------------------------------------------------------
// Kernel 2: deform-GEMM on tensor cores (identical to the 205.6us R8 version).
// ---------------------------------------------------------------------------
#define SM_WHI 0
#define SM_WLO (OO * WPITCH * 2)                 // 74752
#define SM_A   (2 * OO * WPITCH * 2)             // 149504
#define K2_SMEM (SM_A + 2 * A_BUF)               // 231424

__global__ __launch_bounds__(512, 1)
void deform_mma_kernel(const float* __restrict__ x,
                       const float* __restrict__ b_def,
                       float* __restrict__ out)
{
    extern __shared__ char smc[];
    const uint32_t sb = smem_u32(smc);

    const int y0  = blockIdx.x * 2;
    const int b   = blockIdx.y;
    const int tid = threadIdx.x;
    const int warp = tid >> 5;
    const int lane = tid & 31;

    {
        const uint4* src = (const uint4*)g_w2;
        uint4* dst = (uint4*)smc;
        for (int i = tid; i < (2 * OO * WPITCH * 2) / 16; i += 512)
            dst[i] = src[i];
    }

    const int px    = tid & 255;
    const int chg   = (tid >> 8) * 16;
    const int yrow  = y0 + (px >> 7);
    const int gx    = px & 127;
    const float* xb = x + (size_t)b * CC * HWSZ;
    const int ombase = (b * 27 * HH + yrow) * WW + gx;

    const int px0 = warp * 16;

    float acc[8][4];
#pragma unroll
    for (int ob = 0; ob < 8; ob++)
#pragma unroll
        for (int i = 0; i < 4; i++) acc[ob][i] = 0.f;

    const uint32_t a_row  = px0 + (lane & 15);
    const uint32_t a_colb = (lane >> 4) * 16;
    const uint32_t aA = sb + SM_A + a_row * 80 + a_colb;
    const int bg  = lane >> 3;
    const int bl8 = lane & 7;
    const uint32_t b_row_off = ((bg >> 1) * 8 + bl8) * (WPITCH * 2);
    const uint32_t b_k8     = (bg & 1) * 16;

    float cw[4];
    int   ci[4];

    auto compute_params = [&](int tap) {
        float offx = g_om[ombase + tap * HWSZ];
        float offy = g_om[ombase + (9 + tap) * HWSZ];
        float mz   = g_om[ombase + (18 + tap) * HWSZ];
        float m    = 1.f / (1.f + __expf(-mz));
        float ys = (float)(yrow + tap / 3 - 1) + offy;
        float xs = (float)(gx + tap % 3 - 1) + offx;
        float y0f = floorf(ys), x0f = floorf(xs);
        float wy1 = ys - y0f,   wx1 = xs - x0f;
        int iy0 = (int)y0f, ix0 = (int)x0f;
#pragma unroll
        for (int corner = 0; corner < 4; corner++) {
            int oy = corner >> 1, ox = corner & 1;
            int yy = iy0 + oy, xx = ix0 + ox;
            bool valid = (yy >= 0) && (yy < HH) && (xx >= 0) && (xx < WW);
            float wy = oy ? wy1 : (1.f - wy1);
            float wx = ox ? wx1 : (1.f - wx1);
            cw[corner] = valid ? (wy * wx * m) : 0.f;
            ci[corner] = min(max(yy, 0), HH - 1) * WW + min(max(xx, 0), WW - 1);
        }
    };

    auto fill = [&](int pn) {
        const int tapn = pn >> 1;
        const int halfn = pn & 1;
        if (halfn == 0) compute_params(tapn);
        const int cbase = halfn * 32 + chg;
        char* ahp = smc + SM_A + halfn * A_BUF + px * 80 + chg * 2;
        char* alp = ahp + A_HALF;
#pragma unroll
        for (int j = 0; j < 4; j++) {
            float v[4];
#pragma unroll
            for (int q = 0; q < 4; q++) {
                const float* xc = xb + (size_t)(cbase + 4 * j + q) * HWSZ;
                v[q] = cw[0] * __ldg(xc + ci[0]) + cw[1] * __ldg(xc + ci[1])
                     + cw[2] * __ldg(xc + ci[2]) + cw[3] * __ldg(xc + ci[3]);
            }
            uint2 hp, lp;
            split_pack(v, hp, lp);
            *(uint2*)(ahp + 8 * j) = hp;
            *(uint2*)(alp + 8 * j) = lp;
        }
    };

    fill(0);
    __syncthreads();

    for (int p = 0; p < 18; p++) {
        if (p < 17) fill(p + 1);

        const int tap  = p >> 1;
        const int half = p & 1;
        const uint32_t abase = aA + (uint32_t)(half * A_BUF);
#pragma unroll
        for (int ks = 0; ks < 2; ks++) {
            const int kglob = tap * 64 + half * 32 + ks * 16;
            uint32_t ah[4], al[4];
            ldsm4(ah, abase + ks * 32);
            ldsm4(al, abase + A_HALF + ks * 32);
            uint32_t bh[16], bl[16];
            const uint32_t bcol = kglob * 2 + b_k8;
#pragma unroll
            for (int obp = 0; obp < 4; obp++) {
                uint32_t roff = (uint32_t)(obp * 16) * (WPITCH * 2) + b_row_off + bcol;
                ldsm4(&bh[obp * 4], sb + SM_WHI + roff);
                ldsm4(&bl[obp * 4], sb + SM_WLO + roff);
            }
#pragma unroll
            for (int ob = 0; ob < 8; ob++) mma_bf16(acc[ob], ah, &bh[ob * 2]);
#pragma unroll
            for (int ob = 0; ob < 8; ob++) mma_bf16(acc[ob], ah, &bl[ob * 2]);
#pragma unroll
            for (int ob = 0; ob < 8; ob++) mma_bf16(acc[ob], al, &bh[ob * 2]);
        }
        __syncthreads();
    }

    {
        const int prow = px0 + (lane >> 2);
        const int row1 = y0 + (prow >> 7);
        const int x1   = prow & 127;
        const int prow2 = prow + 8;
        const int row2 = y0 + (prow2 >> 7);
        const int x2   = prow2 & 127;
#pragma unroll
        for (int ob = 0; ob < 8; ob++) {
            int o = ob * 8 + (lane & 3) * 2;
            float b0v = __ldg(b_def + o);
            float b1v = __ldg(b_def + o + 1);
            float* p1 = out + (((size_t)(b * OO + o) * HH + row1) * WW + x1);
            float* p2 = out + (((size_t)(b * OO + o) * HH + row2) * WW + x2);
            p1[0]    = fmaxf(acc[ob][0] + b0v, 0.f);
            p1[HWSZ] = fmaxf(acc[ob][1] + b1v, 0.f);
            p2[0]    = fmaxf(acc[ob][2] + b0v, 0.f);
            p2[HWSZ] = fmaxf(acc[ob][3] + b1v, 0.f);
        }
    }
}

// ---------------------------------------------------------------------------
extern "C" void kernel_launch(void* const* d_in, const int* in_sizes, int n_in,
                              void* d_out, int out_size)
{
    const float* x     = (const float*)d_in[0];
    const float* feat  = (const float*)d_in[1];
    const float* w_off = (const float*)d_in[2];
    const float* b_off = (const float*)d_in[3];
    const float* w_def = (const float*)d_in[4];
    const float* b_def = (const float*)d_in[5];
    float* out = (float*)d_out;

    cudaFuncSetAttribute(offset_mma_kernel,
                         cudaFuncAttributeMaxDynamicSharedMemorySize, K1_SMEM);
    cudaFuncSetAttribute(deform_mma_kernel,
                         cudaFuncAttributeMaxDynamicSharedMemorySize, K2_SMEM);

    dim3 gridp(OO + NOFF, 5);
    prep_w_kernel<<<gridp, 128>>>(w_def, w_off);
    dim3 grid1(HH / 2, BB);
    offset_mma_kernel<<<grid1, 512, K1_SMEM>>>(feat, b_off);
    dim3 grid2(HH / 2, BB);
    deform_mma_kernel<<<grid2, 512, K2_SMEM>>>(x, b_def, out);
}

// round 11
// speedup vs baseline: 1.4020x; 1.0832x over previous
#include <cuda_runtime.h>
#include <cuda_bf16.h>
#include <math.h>
#include <stdint.h>

// Problem constants (fixed by setup_inputs)
#define BB   4
#define CC   64
#define OO   64
#define HH   128
#define WW   128
#define HWSZ (HH * WW)

// Scratch: offset-conv output; split weights (def: 64 o, off: 32 o padded)
#define WPITCH 584
#define NOFF   32
__device__ float g_om[BB * 27 * HWSZ];
__device__ unsigned short g_w2[2 * OO * WPITCH];     // w_def hi | lo
__device__ unsigned short g_w1[2 * NOFF * WPITCH];   // w_off hi | lo (o>=27 zero)

__device__ __forceinline__ uint32_t smem_u32(const void* p) {
    uint32_t a;
    asm("{ .reg .u64 t; cvta.to.shared.u64 t, %1; cvt.u32.u64 %0, t; }"
        : "=r"(a) : "l"(p));
    return a;
}
__device__ __forceinline__ void ldsm4(uint32_t* r, uint32_t addr) {
    asm volatile("ldmatrix.sync.aligned.m8n8.x4.shared.b16 {%0,%1,%2,%3}, [%4];"
        : "=r"(r[0]), "=r"(r[1]), "=r"(r[2]), "=r"(r[3]) : "r"(addr));
}
__device__ __forceinline__ void mma_bf16(float* d, const uint32_t* a, const uint32_t* b) {
    asm volatile(
        "mma.sync.aligned.m16n8k16.row.col.f32.bf16.bf16.f32 "
        "{%0,%1,%2,%3}, {%4,%5,%6,%7}, {%8,%9}, {%0,%1,%2,%3};"
        : "+f"(d[0]), "+f"(d[1]), "+f"(d[2]), "+f"(d[3])
        : "r"(a[0]), "r"(a[1]), "r"(a[2]), "r"(a[3]), "r"(b[0]), "r"(b[1]));
}
__device__ __forceinline__ void split_pack(const float* v, uint2& hp, uint2& lp) {
    unsigned short h[4], l[4];
#pragma unroll
    for (int q = 0; q < 4; q++) {
        __nv_bfloat16 hb = __float2bfloat16(v[q]);
        __nv_bfloat16 lb = __float2bfloat16(v[q] - __bfloat162float(hb));
        h[q] = __bfloat16_as_ushort(hb);
        l[q] = __bfloat16_as_ushort(lb);
    }
    hp.x = ((uint32_t)h[1] << 16) | h[0];
    hp.y = ((uint32_t)h[3] << 16) | h[2];
    lp.x = ((uint32_t)l[1] << 16) | l[0];
    lp.y = ((uint32_t)l[3] << 16) | l[2];
}

// named barriers (512 = 256 producers/consumers sync + 256 arrives)
#define NBAR_SYNC(id)   asm volatile("bar.sync %0, 512;"   :: "r"(id) : "memory")
#define NBAR_ARRIVE(id) asm volatile("bar.arrive %0, 512;" :: "r"(id) : "memory")

// ---------------------------------------------------------------------------
// Prep: split w_def (blocks 0..63) and w_off (blocks 64..95) into bf16 hi/lo.
// ---------------------------------------------------------------------------
__global__ void prep_w_kernel(const float* __restrict__ w_def,
                              const float* __restrict__ w_off)
{
    int ob  = blockIdx.x;
    int col = blockIdx.y * 128 + threadIdx.x;
    if (col >= WPITCH) return;
    float w = 0.f;
    if (col < 576) {
        int tap = col >> 6, c = col & 63;
        if (ob < OO) w = w_def[(ob * CC + c) * 9 + tap];
        else if (ob - OO < 27) w = w_off[((ob - OO) * CC + c) * 9 + tap];
    }
    __nv_bfloat16 hb = __float2bfloat16(w);
    __nv_bfloat16 lb = __float2bfloat16(w - __bfloat162float(hb));
    if (ob < OO) {
        g_w2[ob * WPITCH + col] = __bfloat16_as_ushort(hb);
        g_w2[OO * WPITCH + ob * WPITCH + col] = __bfloat16_as_ushort(lb);
    } else {
        int o = ob - OO;
        g_w1[o * WPITCH + col] = __bfloat16_as_ushort(hb);
        g_w1[NOFF * WPITCH + o * WPITCH + col] = __bfloat16_as_ushort(lb);
    }
}

// ---------------------------------------------------------------------------
// Kernel 1 (tensor-core): offset conv as im2col GEMM (unchanged from R10).
// ---------------------------------------------------------------------------
#define A_HALF 20480
#define A_BUF  (2 * A_HALF)
#define K1_SMW  (2 * NOFF * WPITCH * 2)
#define K1_SMA  K1_SMW
#define K1_SMEM (K1_SMA + 2 * A_BUF)

__global__ __launch_bounds__(512, 1)
void offset_mma_kernel(const float* __restrict__ feat,
                       const float* __restrict__ b_off)
{
    extern __shared__ char smc[];
    const uint32_t sb = smem_u32(smc);

    const int y0  = blockIdx.x * 2;
    const int b   = blockIdx.y;
    const int tid = threadIdx.x;
    const int warp = tid >> 5;
    const int lane = tid & 31;

    {
        const uint4* src = (const uint4*)g_w1;
        uint4* dst = (uint4*)smc;
        for (int i = tid; i < K1_SMW / 16; i += 512)
            dst[i] = src[i];
    }

    const int px    = tid & 255;
    const int chg   = (tid >> 8) * 16;
    const int yrow  = y0 + (px >> 7);
    const int gx    = px & 127;
    const float* fb = feat + (size_t)b * CC * HWSZ;

    const int px0 = warp * 16;

    float acc[4][4];
#pragma unroll
    for (int ob = 0; ob < 4; ob++)
#pragma unroll
        for (int i = 0; i < 4; i++) acc[ob][i] = 0.f;

    const uint32_t a_row  = px0 + (lane & 15);
    const uint32_t a_colb = (lane >> 4) * 16;
    const uint32_t aA = sb + K1_SMA + a_row * 80 + a_colb;
    const int bg  = lane >> 3;
    const int bl8 = lane & 7;
    const uint32_t b_row_off = ((bg >> 1) * 8 + bl8) * (WPITCH * 2);
    const uint32_t b_k8     = (bg & 1) * 16;

    auto fill = [&](int pn) {
        const int tapn = pn >> 1;
        const int halfn = pn & 1;
        const int dy = tapn / 3 - 1, dx = tapn % 3 - 1;
        const int yy = yrow + dy, xx = gx + dx;
        const bool valid = (yy >= 0) && (yy < HH) && (xx >= 0) && (xx < WW);
        const int cbase = halfn * 32 + chg;
        const float* fp = fb + (size_t)cbase * HWSZ + yy * WW + xx;
        char* ahp = smc + K1_SMA + halfn * A_BUF + px * 80 + chg * 2;
        char* alp = ahp + A_HALF;
#pragma unroll
        for (int j = 0; j < 4; j++) {
            float v[4];
#pragma unroll
            for (int q = 0; q < 4; q++)
                v[q] = valid ? __ldg(fp + (size_t)(4 * j + q) * HWSZ) : 0.f;
            uint2 hp, lp;
            split_pack(v, hp, lp);
            *(uint2*)(ahp + 8 * j) = hp;
            *(uint2*)(alp + 8 * j) = lp;
        }
    };

    fill(0);
    __syncthreads();

    for (int p = 0; p < 18; p++) {
        if (p < 17) fill(p + 1);

        const int tap  = p >> 1;
        const int half = p & 1;
        const uint32_t abase = aA + (uint32_t)(half * A_BUF);
#pragma unroll
        for (int ks = 0; ks < 2; ks++) {
            const int kglob = tap * 64 + half * 32 + ks * 16;
            uint32_t ah[4], al[4];
            ldsm4(ah, abase + ks * 32);
            ldsm4(al, abase + A_HALF + ks * 32);
            uint32_t bh[8], bl[8];
            const uint32_t bcol = kglob * 2 + b_k8;
#pragma unroll
            for (int obp = 0; obp < 2; obp++) {
                uint32_t roff = (uint32_t)(obp * 16) * (WPITCH * 2) + b_row_off + bcol;
                ldsm4(&bh[obp * 4], sb + roff);
                ldsm4(&bl[obp * 4], sb + (uint32_t)(NOFF * WPITCH * 2) + roff);
            }
#pragma unroll
            for (int ob = 0; ob < 4; ob++) mma_bf16(acc[ob], ah, &bh[ob * 2]);
#pragma unroll
            for (int ob = 0; ob < 4; ob++) mma_bf16(acc[ob], ah, &bl[ob * 2]);
#pragma unroll
            for (int ob = 0; ob < 4; ob++) mma_bf16(acc[ob], al, &bh[ob * 2]);
        }
        __syncthreads();
    }

    {
        const int prow = px0 + (lane >> 2);
        const int row1 = y0 + (prow >> 7);
        const int x1   = prow & 127;
        const int prow2 = prow + 8;
        const int row2 = y0 + (prow2 >> 7);
        const int x2   = prow2 & 127;
#pragma unroll
        for (int ob = 0; ob < 4; ob++) {
            int o = ob * 8 + (lane & 3) * 2;
            if (o < 27) {
                float bv = __ldg(b_off + o);
                g_om[((b * 27 + o) * HH + row1) * WW + x1] = acc[ob][0] + bv;
                g_om[((b * 27 + o) * HH + row2) * WW + x2] = acc[ob][2] + bv;
            }
            if (o + 1 < 27) {
                float bv = __ldg(b_off + o + 1);
                g_om[((b * 27 + o + 1) * HH + row1) * WW + x1] = acc[ob][1] + bv;
                g_om[((b * 27 + o + 1) * HH + row2) * WW + x2] = acc[ob][3] + bv;
            }
        }
    }
}

// ---------------------------------------------------------------------------
// Kernel 2: WARP-SPECIALIZED deform-GEMM.
// 512 threads: warps 0-7 = consumers (mma), warps 8-15 = producers (gather).
// Ring: 3 stages x (A tile 256 px x 16 ch, hi+lo, pitch 48B). 36 phases
// (9 taps x 4 quarters of 16 ch). full[s]=bar 1+s, empty[s]=bar 4+s.
// smem: Whi+Wlo 149504 + 3 x 24576 = 223232 B.
// ---------------------------------------------------------------------------
#define SM_WHI 0
#define SM_WLO (OO * WPITCH * 2)
#define SM_A   (2 * OO * WPITCH * 2)             // 149504
#define STG_HALF 12288                           // 256*48
#define STG      (2 * STG_HALF)                  // hi+lo
#define K2_SMEM (SM_A + 3 * STG)                 // 223232

__global__ __launch_bounds__(512, 1)
void deform_mma_kernel(const float* __restrict__ x,
                       const float* __restrict__ b_def,
                       float* __restrict__ out)
{
    extern __shared__ char smc[];
    const uint32_t sb = smem_u32(smc);

    const int y0  = blockIdx.x * 2;
    const int b   = blockIdx.y;
    const int tid = threadIdx.x;
    const int warp = tid >> 5;
    const int lane = tid & 31;

    // stage split weights (all 512 threads)
    {
        const uint4* src = (const uint4*)g_w2;
        uint4* dst = (uint4*)smc;
        for (int i = tid; i < (2 * OO * WPITCH * 2) / 16; i += 512)
            dst[i] = src[i];
    }
    __syncthreads();

    if (warp >= 8) {
        // ---------------- producer ----------------
        const int px   = (warp - 8) * 32 + lane;    // 0..255
        const int yrow = y0 + (px >> 7);
        const int gx   = px & 127;
        const float* xb = x + (size_t)b * CC * HWSZ;
        const int ombase = (b * 27 * HH + yrow) * WW + gx;

        float cw0, cw1, cw2, cw3;
        int   ci0, ci1, ci2, ci3;
        int s = 0;
        for (int p = 0; p < 36; p++) {
            const int tap = p >> 2;
            const int q   = p & 3;
            if (q == 0) {
                float offx = g_om[ombase + tap * HWSZ];
                float offy = g_om[ombase + (9 + tap) * HWSZ];
                float mz   = g_om[ombase + (18 + tap) * HWSZ];
                float m    = 1.f / (1.f + __expf(-mz));
                float ys = (float)(yrow + tap / 3 - 1) + offy;
                float xs = (float)(gx + tap % 3 - 1) + offx;
                float y0f = floorf(ys), x0f = floorf(xs);
                float wy1 = ys - y0f, wx1 = xs - x0f;
                int iy0 = (int)y0f, ix0 = (int)x0f;
                bool vy0 = (iy0 >= 0) && (iy0 < HH);
                bool vy1 = (iy0 + 1 >= 0) && (iy0 + 1 < HH);
                bool vx0 = (ix0 >= 0) && (ix0 < WW);
                bool vx1 = (ix0 + 1 >= 0) && (ix0 + 1 < WW);
                cw0 = (vy0 && vx0) ? (1.f - wy1) * (1.f - wx1) * m : 0.f;
                cw1 = (vy0 && vx1) ? (1.f - wy1) * wx1 * m : 0.f;
                cw2 = (vy1 && vx0) ? wy1 * (1.f - wx1) * m : 0.f;
                cw3 = (vy1 && vx1) ? wy1 * wx1 * m : 0.f;
                int y0c = min(max(iy0, 0), HH - 1);
                int y1c = min(max(iy0 + 1, 0), HH - 1);
                int x0c = min(max(ix0, 0), WW - 1);
                int x1c = min(max(ix0 + 1, 0), WW - 1);
                ci0 = y0c * WW + x0c;  ci1 = y0c * WW + x1c;
                ci2 = y1c * WW + x0c;  ci3 = y1c * WW + x1c;
            }
            if (p >= 3) NBAR_SYNC(4 + s);          // wait stage empty

            const int cbase = q * 16;
            const float* xc0 = xb + (size_t)cbase * HWSZ;
            char* ahp = smc + SM_A + s * STG + px * 48;
            char* alp = ahp + STG_HALF;
            uint2 hp[4], lp[4];
#pragma unroll
            for (int j = 0; j < 4; j++) {
                float v[4];
#pragma unroll
                for (int qq = 0; qq < 4; qq++) {
                    const float* xc = xc0 + (size_t)(4 * j + qq) * HWSZ;
                    v[qq] = cw0 * __ldg(xc + ci0) + cw1 * __ldg(xc + ci1)
                          + cw2 * __ldg(xc + ci2) + cw3 * __ldg(xc + ci3);
                }
                split_pack(v, hp[j], lp[j]);
            }
            *(uint4*)(ahp)      = make_uint4(hp[0].x, hp[0].y, hp[1].x, hp[1].y);
            *(uint4*)(ahp + 16) = make_uint4(hp[2].x, hp[2].y, hp[3].x, hp[3].y);
            *(uint4*)(alp)      = make_uint4(lp[0].x, lp[0].y, lp[1].x, lp[1].y);
            *(uint4*)(alp + 16) = make_uint4(lp[2].x, lp[2].y, lp[3].x, lp[3].y);

            NBAR_ARRIVE(1 + s);                    // stage full
            if (++s == 3) s = 0;
        }
    } else {
        // ---------------- consumer ----------------
        float acc[2][8][4];
#pragma unroll
        for (int t = 0; t < 2; t++)
#pragma unroll
            for (int ob = 0; ob < 8; ob++)
#pragma unroll
                for (int i = 0; i < 4; i++) acc[t][ob][i] = 0.f;

        const uint32_t aBase = sb + SM_A
            + (uint32_t)(warp * 32 + (lane & 15)) * 48 + (uint32_t)((lane >> 4) * 16);
        const int bg  = lane >> 3;
        const int bl8 = lane & 7;
        const uint32_t b_row_off = ((bg >> 1) * 8 + bl8) * (WPITCH * 2);
        const uint32_t b_k8     = (bg & 1) * 16;

        int s = 0;
        for (int p = 0; p < 36; p++) {
            const int tap = p >> 2;
            const int q   = p & 3;
            NBAR_SYNC(1 + s);                      // wait stage full

            const uint32_t stoff = (uint32_t)(s * STG);
            uint32_t ah[2][4], al[2][4];
            ldsm4(ah[0], aBase + stoff);
            ldsm4(ah[1], aBase + stoff + 16 * 48);
            ldsm4(al[0], aBase + stoff + STG_HALF);
            ldsm4(al[1], aBase + stoff + STG_HALF + 16 * 48);

            const uint32_t bcol = (uint32_t)(tap * 64 + q * 16) * 2 + b_k8;
#pragma unroll
            for (int half = 0; half < 2; half++) {
                uint32_t bh[8], bl[8];
#pragma unroll
                for (int oi = 0; oi < 2; oi++) {
                    int obp = half * 2 + oi;
                    uint32_t roff = (uint32_t)(obp * 16) * (WPITCH * 2) + b_row_off + bcol;
                    ldsm4(&bh[oi * 4], sb + SM_WHI + roff);
                    ldsm4(&bl[oi * 4], sb + SM_WLO + roff);
                }
#pragma unroll
                for (int t = 0; t < 2; t++)
#pragma unroll
                    for (int obl = 0; obl < 4; obl++) {
                        float* a = acc[t][half * 4 + obl];
                        mma_bf16(a, ah[t], &bh[obl * 2]);
                        mma_bf16(a, ah[t], &bl[obl * 2]);
                        mma_bf16(a, al[t], &bh[obl * 2]);
                    }
            }
            if (p < 33) NBAR_ARRIVE(4 + s);        // stage empty
            if (++s == 3) s = 0;
        }

        // epilogue: bias + relu
#pragma unroll
        for (int t = 0; t < 2; t++) {
            const int prow = warp * 32 + t * 16 + (lane >> 2);
            const int row1 = y0 + (prow >> 7);
            const int x1   = prow & 127;
            const int prow2 = prow + 8;
            const int row2 = y0 + (prow2 >> 7);
            const int x2   = prow2 & 127;
#pragma unroll
            for (int ob = 0; ob < 8; ob++) {
                int o = ob * 8 + (lane & 3) * 2;
                float b0v = __ldg(b_def + o);
                float b1v = __ldg(b_def + o + 1);
                float* p1 = out + (((size_t)(b * OO + o) * HH + row1) * WW + x1);
                float* p2 = out + (((size_t)(b * OO + o) * HH + row2) * WW + x2);
                p1[0]    = fmaxf(acc[t][ob][0] + b0v, 0.f);
                p1[HWSZ] = fmaxf(acc[t][ob][1] + b1v, 0.f);
                p2[0]    = fmaxf(acc[t][ob][2] + b0v, 0.f);
                p2[HWSZ] = fmaxf(acc[t][ob][3] + b1v, 0.f);
            }
        }
    }
}

// ---------------------------------------------------------------------------
extern "C" void kernel_launch(void* const* d_in, const int* in_sizes, int n_in,
                              void* d_out, int out_size)
{
    const float* x     = (const float*)d_in[0];
    const float* feat  = (const float*)d_in[1];
    const float* w_off = (const float*)d_in[2];
    const float* b_off = (const float*)d_in[3];
    const float* w_def = (const float*)d_in[4];
    const float* b_def = (const float*)d_in[5];
    float* out = (float*)d_out;

    cudaFuncSetAttribute(offset_mma_kernel,
                         cudaFuncAttributeMaxDynamicSharedMemorySize, K1_SMEM);
    cudaFuncSetAttribute(deform_mma_kernel,
                         cudaFuncAttributeMaxDynamicSharedMemorySize, K2_SMEM);

    dim3 gridp(OO + NOFF, 5);
    prep_w_kernel<<<gridp, 128>>>(w_def, w_off);
    dim3 grid1(HH / 2, BB);
    offset_mma_kernel<<<grid1, 512, K1_SMEM>>>(feat, b_off);
    dim3 grid2(HH / 2, BB);
    deform_mma_kernel<<<grid2, 512, K2_SMEM>>>(x, b_def, out);
}

// round 12
// speedup vs baseline: 1.4377x; 1.0255x over previous
#include <cuda_runtime.h>
#include <cuda_bf16.h>
#include <math.h>
#include <stdint.h>

// Problem constants (fixed by setup_inputs)
#define BB   4
#define CC   64
#define OO   64
#define HH   128
#define WW   128
#define HWSZ (HH * WW)

// Scratch: offset-conv output; split weights (def: 64 o, off: 32 o padded)
#define WPITCH 584
#define NOFF   32
__device__ float g_om[BB * 27 * HWSZ];
__device__ unsigned short g_w2[2 * OO * WPITCH];     // w_def hi | lo
__device__ unsigned short g_w1[2 * NOFF * WPITCH];   // w_off hi | lo (o>=27 zero)

__device__ __forceinline__ uint32_t smem_u32(const void* p) {
    uint32_t a;
    asm("{ .reg .u64 t; cvta.to.shared.u64 t, %1; cvt.u32.u64 %0, t; }"
        : "=r"(a) : "l"(p));
    return a;
}
__device__ __forceinline__ void ldsm4(uint32_t* r, uint32_t addr) {
    asm volatile("ldmatrix.sync.aligned.m8n8.x4.shared.b16 {%0,%1,%2,%3}, [%4];"
        : "=r"(r[0]), "=r"(r[1]), "=r"(r[2]), "=r"(r[3]) : "r"(addr));
}
__device__ __forceinline__ void mma_bf16(float* d, const uint32_t* a, const uint32_t* b) {
    asm volatile(
        "mma.sync.aligned.m16n8k16.row.col.f32.bf16.bf16.f32 "
        "{%0,%1,%2,%3}, {%4,%5,%6,%7}, {%8,%9}, {%0,%1,%2,%3};"
        : "+f"(d[0]), "+f"(d[1]), "+f"(d[2]), "+f"(d[3])
        : "r"(a[0]), "r"(a[1]), "r"(a[2]), "r"(a[3]), "r"(b[0]), "r"(b[1]));
}
__device__ __forceinline__ void split_pack(const float* v, uint2& hp, uint2& lp) {
    unsigned short h[4], l[4];
#pragma unroll
    for (int q = 0; q < 4; q++) {
        __nv_bfloat16 hb = __float2bfloat16(v[q]);
        __nv_bfloat16 lb = __float2bfloat16(v[q] - __bfloat162float(hb));
        h[q] = __bfloat16_as_ushort(hb);
        l[q] = __bfloat16_as_ushort(lb);
    }
    hp.x = ((uint32_t)h[1] << 16) | h[0];
    hp.y = ((uint32_t)h[3] << 16) | h[2];
    lp.x = ((uint32_t)l[1] << 16) | l[0];
    lp.y = ((uint32_t)l[3] << 16) | l[2];
}

// named barriers (512 = producers + consumers)
#define NBAR_SYNC(id)   asm volatile("bar.sync %0, 512;"   :: "r"(id) : "memory")
#define NBAR_ARRIVE(id) asm volatile("bar.arrive %0, 512;" :: "r"(id) : "memory")

// ---------------------------------------------------------------------------
// Prep: split w_def (blocks 0..63) and w_off (blocks 64..95) into bf16 hi/lo.
// ---------------------------------------------------------------------------
__global__ void prep_w_kernel(const float* __restrict__ w_def,
                              const float* __restrict__ w_off)
{
    int ob  = blockIdx.x;
    int col = blockIdx.y * 128 + threadIdx.x;
    if (col >= WPITCH) return;
    float w = 0.f;
    if (col < 576) {
        int tap = col >> 6, c = col & 63;
        if (ob < OO) w = w_def[(ob * CC + c) * 9 + tap];
        else if (ob - OO < 27) w = w_off[((ob - OO) * CC + c) * 9 + tap];
    }
    __nv_bfloat16 hb = __float2bfloat16(w);
    __nv_bfloat16 lb = __float2bfloat16(w - __bfloat162float(hb));
    if (ob < OO) {
        g_w2[ob * WPITCH + col] = __bfloat16_as_ushort(hb);
        g_w2[OO * WPITCH + ob * WPITCH + col] = __bfloat16_as_ushort(lb);
    } else {
        int o = ob - OO;
        g_w1[o * WPITCH + col] = __bfloat16_as_ushort(hb);
        g_w1[NOFF * WPITCH + o * WPITCH + col] = __bfloat16_as_ushort(lb);
    }
}

// ---------------------------------------------------------------------------
// Ring geometry (shared by both kernels): 3 stages x (256 px x 16 ch, hi+lo),
// pitch 48 B. full[s] = bar 1+s, empty[s] = bar 4+s. 36 phases.
// ---------------------------------------------------------------------------
#define STG_HALF 12288                           // 256*48
#define STG      (2 * STG_HALF)

// ---------------------------------------------------------------------------
// Kernel 1: offset conv, WARP-SPECIALIZED im2col GEMM. N=32 (27 used).
// smem: W (74752) + 3 x STG (73728) = 148480 B.
// ---------------------------------------------------------------------------
#define K1_SMW  (2 * NOFF * WPITCH * 2)          // 74752
#define K1_SMA  K1_SMW
#define K1_SMEM (K1_SMA + 3 * STG)

__global__ __launch_bounds__(512, 1)
void offset_mma_kernel(const float* __restrict__ feat,
                       const float* __restrict__ b_off)
{
    extern __shared__ char smc[];
    const uint32_t sb = smem_u32(smc);

    const int y0  = blockIdx.x * 2;
    const int b   = blockIdx.y;
    const int tid = threadIdx.x;
    const int warp = tid >> 5;
    const int lane = tid & 31;

    {
        const uint4* src = (const uint4*)g_w1;
        uint4* dst = (uint4*)smc;
        for (int i = tid; i < K1_SMW / 16; i += 512)
            dst[i] = src[i];
    }
    __syncthreads();

    if (warp >= 8) {
        // ---------------- producer: coalesced shifted feat reads ----------
        const int px   = (warp - 8) * 32 + lane;
        const int yrow = y0 + (px >> 7);
        const int gx   = px & 127;
        const float* fb = feat + (size_t)b * CC * HWSZ;

        int s = 0;
        for (int p = 0; p < 36; p++) {
            const int tap = p >> 2;
            const int q   = p & 3;
            const int dy = tap / 3 - 1, dx = tap % 3 - 1;
            const int yy = yrow + dy, xx = gx + dx;
            const bool valid = (yy >= 0) && (yy < HH) && (xx >= 0) && (xx < WW);
            const float* fp = fb + (size_t)(q * 16) * HWSZ + yy * WW + xx;

            if (p >= 3) NBAR_SYNC(4 + s);

            char* ahp = smc + K1_SMA + s * STG + px * 48;
            char* alp = ahp + STG_HALF;
            uint2 hp[4], lp[4];
#pragma unroll
            for (int j = 0; j < 4; j++) {
                float v[4];
#pragma unroll
                for (int qq = 0; qq < 4; qq++)
                    v[qq] = valid ? __ldg(fp + (size_t)(4 * j + qq) * HWSZ) : 0.f;
                split_pack(v, hp[j], lp[j]);
            }
            *(uint4*)(ahp)      = make_uint4(hp[0].x, hp[0].y, hp[1].x, hp[1].y);
            *(uint4*)(ahp + 16) = make_uint4(hp[2].x, hp[2].y, hp[3].x, hp[3].y);
            *(uint4*)(alp)      = make_uint4(lp[0].x, lp[0].y, lp[1].x, lp[1].y);
            *(uint4*)(alp + 16) = make_uint4(lp[2].x, lp[2].y, lp[3].x, lp[3].y);

            NBAR_ARRIVE(1 + s);
            if (++s == 3) s = 0;
        }
    } else {
        // ---------------- consumer: 32 px x 32 o ----------------
        float acc[2][4][4];
#pragma unroll
        for (int t = 0; t < 2; t++)
#pragma unroll
            for (int ob = 0; ob < 4; ob++)
#pragma unroll
                for (int i = 0; i < 4; i++) acc[t][ob][i] = 0.f;

        const uint32_t aBase = sb + K1_SMA
            + (uint32_t)(warp * 32 + (lane & 15)) * 48 + (uint32_t)((lane >> 4) * 16);
        const int bg  = lane >> 3;
        const int bl8 = lane & 7;
        const uint32_t b_row_off = ((bg >> 1) * 8 + bl8) * (WPITCH * 2);
        const uint32_t b_k8     = (bg & 1) * 16;

        int s = 0;
        for (int p = 0; p < 36; p++) {
            const int tap = p >> 2;
            const int q   = p & 3;
            NBAR_SYNC(1 + s);

            const uint32_t stoff = (uint32_t)(s * STG);
            uint32_t ah[2][4], al[2][4];
            ldsm4(ah[0], aBase + stoff);
            ldsm4(ah[1], aBase + stoff + 16 * 48);
            ldsm4(al[0], aBase + stoff + STG_HALF);
            ldsm4(al[1], aBase + stoff + STG_HALF + 16 * 48);
            if (p < 33) NBAR_ARRIVE(4 + s);   // stage free once A frags in regs

            const uint32_t bcol = (uint32_t)(tap * 64 + q * 16) * 2 + b_k8;
            uint32_t bh[8], bl[8];
#pragma unroll
            for (int oi = 0; oi < 2; oi++) {
                uint32_t roff = (uint32_t)(oi * 16) * (WPITCH * 2) + b_row_off + bcol;
                ldsm4(&bh[oi * 4], sb + roff);
                ldsm4(&bl[oi * 4], sb + (uint32_t)(NOFF * WPITCH * 2) + roff);
            }
#pragma unroll
            for (int t = 0; t < 2; t++)
#pragma unroll
                for (int obl = 0; obl < 4; obl++) {
                    float* a = acc[t][obl];
                    mma_bf16(a, ah[t], &bh[obl * 2]);
                    mma_bf16(a, ah[t], &bl[obl * 2]);
                    mma_bf16(a, al[t], &bh[obl * 2]);
                }
            if (++s == 3) s = 0;
        }

        // epilogue: bias, store to g_om; only o < 27
#pragma unroll
        for (int t = 0; t < 2; t++) {
            const int prow = warp * 32 + t * 16 + (lane >> 2);
            const int row1 = y0 + (prow >> 7);
            const int x1   = prow & 127;
            const int prow2 = prow + 8;
            const int row2 = y0 + (prow2 >> 7);
            const int x2   = prow2 & 127;
#pragma unroll
            for (int ob = 0; ob < 4; ob++) {
                int o = ob * 8 + (lane & 3) * 2;
                if (o < 27) {
                    float bv = __ldg(b_off + o);
                    g_om[((b * 27 + o) * HH + row1) * WW + x1] = acc[t][ob][0] + bv;
                    g_om[((b * 27 + o) * HH + row2) * WW + x2] = acc[t][ob][2] + bv;
                }
                if (o + 1 < 27) {
                    float bv = __ldg(b_off + o + 1);
                    g_om[((b * 27 + o + 1) * HH + row1) * WW + x1] = acc[t][ob][1] + bv;
                    g_om[((b * 27 + o + 1) * HH + row2) * WW + x2] = acc[t][ob][3] + bv;
                }
            }
        }
    }
}

// ---------------------------------------------------------------------------
// Kernel 2: WARP-SPECIALIZED deform-GEMM (R11 + early empty-arrive).
// smem: Whi+Wlo 149504 + 3 x 24576 = 223232 B.
// ---------------------------------------------------------------------------
#define SM_WHI 0
#define SM_WLO (OO * WPITCH * 2)
#define SM_A   (2 * OO * WPITCH * 2)             // 149504
#define K2_SMEM (SM_A + 3 * STG)                 // 223232

__global__ __launch_bounds__(512, 1)
void deform_mma_kernel(const float* __restrict__ x,
                       const float* __restrict__ b_def,
                       float* __restrict__ out)
{
    extern __shared__ char smc[];
    const uint32_t sb = smem_u32(smc);

    const int y0  = blockIdx.x * 2;
    const int b   = blockIdx.y;
    const int tid = threadIdx.x;
    const int warp = tid >> 5;
    const int lane = tid & 31;

    {
        const uint4* src = (const uint4*)g_w2;
        uint4* dst = (uint4*)smc;
        for (int i = tid; i < (2 * OO * WPITCH * 2) / 16; i += 512)
            dst[i] = src[i];
    }
    __syncthreads();

    if (warp >= 8) {
        // ---------------- producer ----------------
        const int px   = (warp - 8) * 32 + lane;
        const int yrow = y0 + (px >> 7);
        const int gx   = px & 127;
        const float* xb = x + (size_t)b * CC * HWSZ;
        const int ombase = (b * 27 * HH + yrow) * WW + gx;

        float cw0, cw1, cw2, cw3;
        int   ci0, ci1, ci2, ci3;
        int s = 0;
        for (int p = 0; p < 36; p++) {
            const int tap = p >> 2;
            const int q   = p & 3;
            if (q == 0) {
                float offx = g_om[ombase + tap * HWSZ];
                float offy = g_om[ombase + (9 + tap) * HWSZ];
                float mz   = g_om[ombase + (18 + tap) * HWSZ];
                float m    = 1.f / (1.f + __expf(-mz));
                float ys = (float)(yrow + tap / 3 - 1) + offy;
                float xs = (float)(gx + tap % 3 - 1) + offx;
                float y0f = floorf(ys), x0f = floorf(xs);
                float wy1 = ys - y0f, wx1 = xs - x0f;
                int iy0 = (int)y0f, ix0 = (int)x0f;
                bool vy0 = (iy0 >= 0) && (iy0 < HH);
                bool vy1 = (iy0 + 1 >= 0) && (iy0 + 1 < HH);
                bool vx0 = (ix0 >= 0) && (ix0 < WW);
                bool vx1 = (ix0 + 1 >= 0) && (ix0 + 1 < WW);
                cw0 = (vy0 && vx0) ? (1.f - wy1) * (1.f - wx1) * m : 0.f;
                cw1 = (vy0 && vx1) ? (1.f - wy1) * wx1 * m : 0.f;
                cw2 = (vy1 && vx0) ? wy1 * (1.f - wx1) * m : 0.f;
                cw3 = (vy1 && vx1) ? wy1 * wx1 * m : 0.f;
                int y0c = min(max(iy0, 0), HH - 1);
                int y1c = min(max(iy0 + 1, 0), HH - 1);
                int x0c = min(max(ix0, 0), WW - 1);
                int x1c = min(max(ix0 + 1, 0), WW - 1);
                ci0 = y0c * WW + x0c;  ci1 = y0c * WW + x1c;
                ci2 = y1c * WW + x0c;  ci3 = y1c * WW + x1c;
            }
            if (p >= 3) NBAR_SYNC(4 + s);

            const float* xc0 = xb + (size_t)(q * 16) * HWSZ;
            char* ahp = smc + SM_A + s * STG + px * 48;
            char* alp = ahp + STG_HALF;
            uint2 hp[4], lp[4];
#pragma unroll
            for (int j = 0; j < 4; j++) {
                float v[4];
#pragma unroll
                for (int qq = 0; qq < 4; qq++) {
                    const float* xc = xc0 + (size_t)(4 * j + qq) * HWSZ;
                    v[qq] = cw0 * __ldg(xc + ci0) + cw1 * __ldg(xc + ci1)
                          + cw2 * __ldg(xc + ci2) + cw3 * __ldg(xc + ci3);
                }
                split_pack(v, hp[j], lp[j]);
            }
            *(uint4*)(ahp)      = make_uint4(hp[0].x, hp[0].y, hp[1].x, hp[1].y);
            *(uint4*)(ahp + 16) = make_uint4(hp[2].x, hp[2].y, hp[3].x, hp[3].y);
            *(uint4*)(alp)      = make_uint4(lp[0].x, lp[0].y, lp[1].x, lp[1].y);
            *(uint4*)(alp + 16) = make_uint4(lp[2].x, lp[2].y, lp[3].x, lp[3].y);

            NBAR_ARRIVE(1 + s);
            if (++s == 3) s = 0;
        }
    } else {
        // ---------------- consumer ----------------
        float acc[2][8][4];
#pragma unroll
        for (int t = 0; t < 2; t++)
#pragma unroll
            for (int ob = 0; ob < 8; ob++)
#pragma unroll
                for (int i = 0; i < 4; i++) acc[t][ob][i] = 0.f;

        const uint32_t aBase = sb + SM_A
            + (uint32_t)(warp * 32 + (lane & 15)) * 48 + (uint32_t)((lane >> 4) * 16);
        const int bg  = lane >> 3;
        const int bl8 = lane & 7;
        const uint32_t b_row_off = ((bg >> 1) * 8 + bl8) * (WPITCH * 2);
        const uint32_t b_k8     = (bg & 1) * 16;

        int s = 0;
        for (int p = 0; p < 36; p++) {
            const int tap = p >> 2;
            const int q   = p & 3;
            NBAR_SYNC(1 + s);

            const uint32_t stoff = (uint32_t)(s * STG);
            uint32_t ah[2][4], al[2][4];
            ldsm4(ah[0], aBase + stoff);
            ldsm4(ah[1], aBase + stoff + 16 * 48);
            ldsm4(al[0], aBase + stoff + STG_HALF);
            ldsm4(al[1], aBase + stoff + STG_HALF + 16 * 48);
            if (p < 33) NBAR_ARRIVE(4 + s);   // stage free once A frags in regs

            const uint32_t bcol = (uint32_t)(tap * 64 + q * 16) * 2 + b_k8;
#pragma unroll
            for (int half = 0; half < 2; half++) {
                uint32_t bh[8], bl[8];
#pragma unroll
                for (int oi = 0; oi < 2; oi++) {
                    int obp = half * 2 + oi;
                    uint32_t roff = (uint32_t)(obp * 16) * (WPITCH * 2) + b_row_off + bcol;
                    ldsm4(&bh[oi * 4], sb + SM_WHI + roff);
                    ldsm4(&bl[oi * 4], sb + SM_WLO + roff);
                }
#pragma unroll
                for (int t = 0; t < 2; t++)
#pragma unroll
                    for (int obl = 0; obl < 4; obl++) {
                        float* a = acc[t][half * 4 + obl];
                        mma_bf16(a, ah[t], &bh[obl * 2]);
                        mma_bf16(a, ah[t], &bl[obl * 2]);
                        mma_bf16(a, al[t], &bh[obl * 2]);
                    }
            }
            if (++s == 3) s = 0;
        }

        // epilogue: bias + relu
#pragma unroll
        for (int t = 0; t < 2; t++) {
            const int prow = warp * 32 + t * 16 + (lane >> 2);
            const int row1 = y0 + (prow >> 7);
            const int x1   = prow & 127;
            const int prow2 = prow + 8;
            const int row2 = y0 + (prow2 >> 7);
            const int x2   = prow2 & 127;
#pragma unroll
            for (int ob = 0; ob < 8; ob++) {
                int o = ob * 8 + (lane & 3) * 2;
                float b0v = __ldg(b_def + o);
                float b1v = __ldg(b_def + o + 1);
                float* p1 = out + (((size_t)(b * OO + o) * HH + row1) * WW + x1);
                float* p2 = out + (((size_t)(b * OO + o) * HH + row2) * WW + x2);
                p1[0]    = fmaxf(acc[t][ob][0] + b0v, 0.f);
                p1[HWSZ] = fmaxf(acc[t][ob][1] + b1v, 0.f);
                p2[0]    = fmaxf(acc[t][ob][2] + b0v, 0.f);
                p2[HWSZ] = fmaxf(acc[t][ob][3] + b1v, 0.f);
            }
        }
    }
}

// ---------------------------------------------------------------------------
extern "C" void kernel_launch(void* const* d_in, const int* in_sizes, int n_in,
                              void* d_out, int out_size)
{
    const float* x     = (const float*)d_in[0];
    const float* feat  = (const float*)d_in[1];
    const float* w_off = (const float*)d_in[2];
    const float* b_off = (const float*)d_in[3];
    const float* w_def = (const float*)d_in[4];
    const float* b_def = (const float*)d_in[5];
    float* out = (float*)d_out;

    cudaFuncSetAttribute(offset_mma_kernel,
                         cudaFuncAttributeMaxDynamicSharedMemorySize, K1_SMEM);
    cudaFuncSetAttribute(deform_mma_kernel,
                         cudaFuncAttributeMaxDynamicSharedMemorySize, K2_SMEM);

    dim3 gridp(OO + NOFF, 5);
    prep_w_kernel<<<gridp, 128>>>(w_def, w_off);
    dim3 grid1(HH / 2, BB);
    offset_mma_kernel<<<grid1, 512, K1_SMEM>>>(feat, b_off);
    dim3 grid2(HH / 2, BB);
    deform_mma_kernel<<<grid2, 512, K2_SMEM>>>(x, b_def, out);
}

// round 13
// speedup vs baseline: 1.5307x; 1.0647x over previous
#include <cuda_runtime.h>
#include <cuda_bf16.h>
#include <math.h>
#include <stdint.h>

// Problem constants (fixed by setup_inputs)
#define BB   4
#define CC   64
#define OO   64
#define HH   128
#define WW   128
#define HWSZ (HH * WW)

// Scratch: offset-conv output; split weights (def: 64 o, off: 32 o padded)
#define WPITCH 584
#define NOFF   32
__device__ float g_om[BB * 27 * HWSZ];
__device__ unsigned short g_w2[2 * OO * WPITCH];     // w_def hi | lo
__device__ unsigned short g_w1[2 * NOFF * WPITCH];   // w_off hi | lo (o>=27 zero)

__device__ __forceinline__ uint32_t smem_u32(const void* p) {
    uint32_t a;
    asm("{ .reg .u64 t; cvta.to.shared.u64 t, %1; cvt.u32.u64 %0, t; }"
        : "=r"(a) : "l"(p));
    return a;
}
__device__ __forceinline__ void ldsm4(uint32_t* r, uint32_t addr) {
    asm volatile("ldmatrix.sync.aligned.m8n8.x4.shared.b16 {%0,%1,%2,%3}, [%4];"
        : "=r"(r[0]), "=r"(r[1]), "=r"(r[2]), "=r"(r[3]) : "r"(addr));
}
__device__ __forceinline__ void mma_bf16(float* d, const uint32_t* a, const uint32_t* b) {
    asm volatile(
        "mma.sync.aligned.m16n8k16.row.col.f32.bf16.bf16.f32 "
        "{%0,%1,%2,%3}, {%4,%5,%6,%7}, {%8,%9}, {%0,%1,%2,%3};"
        : "+f"(d[0]), "+f"(d[1]), "+f"(d[2]), "+f"(d[3])
        : "r"(a[0]), "r"(a[1]), "r"(a[2]), "r"(a[3]), "r"(b[0]), "r"(b[1]));
}
__device__ __forceinline__ void split_pack(const float* v, uint2& hp, uint2& lp) {
    unsigned short h[4], l[4];
#pragma unroll
    for (int q = 0; q < 4; q++) {
        __nv_bfloat16 hb = __float2bfloat16(v[q]);
        __nv_bfloat16 lb = __float2bfloat16(v[q] - __bfloat162float(hb));
        h[q] = __bfloat16_as_ushort(hb);
        l[q] = __bfloat16_as_ushort(lb);
    }
    hp.x = ((uint32_t)h[1] << 16) | h[0];
    hp.y = ((uint32_t)h[3] << 16) | h[2];
    lp.x = ((uint32_t)l[1] << 16) | l[0];
    lp.y = ((uint32_t)l[3] << 16) | l[2];
}

// named barriers (512 = producers + consumers)
#define NBAR_SYNC(id)   asm volatile("bar.sync %0, 512;"   :: "r"(id) : "memory")
#define NBAR_ARRIVE(id) asm volatile("bar.arrive %0, 512;" :: "r"(id) : "memory")

// ---------------------------------------------------------------------------
// Prep: split w_def (blocks 0..63) and w_off (blocks 64..95) into bf16 hi/lo.
// ---------------------------------------------------------------------------
__global__ void prep_w_kernel(const float* __restrict__ w_def,
                              const float* __restrict__ w_off)
{
    int ob  = blockIdx.x;
    int col = blockIdx.y * 128 + threadIdx.x;
    if (col >= WPITCH) return;
    float w = 0.f;
    if (col < 576) {
        int tap = col >> 6, c = col & 63;
        if (ob < OO) w = w_def[(ob * CC + c) * 9 + tap];
        else if (ob - OO < 27) w = w_off[((ob - OO) * CC + c) * 9 + tap];
    }
    __nv_bfloat16 hb = __float2bfloat16(w);
    __nv_bfloat16 lb = __float2bfloat16(w - __bfloat162float(hb));
    if (ob < OO) {
        g_w2[ob * WPITCH + col] = __bfloat16_as_ushort(hb);
        g_w2[OO * WPITCH + ob * WPITCH + col] = __bfloat16_as_ushort(lb);
    } else {
        int o = ob - OO;
        g_w1[o * WPITCH + col] = __bfloat16_as_ushort(hb);
        g_w1[NOFF * WPITCH + o * WPITCH + col] = __bfloat16_as_ushort(lb);
    }
}

// ---------------------------------------------------------------------------
// Shared geometry.
// Ring: 3 stages x (256 px x 16 ch, hi+lo), pitch 48 B, at smem offset 0.
// W slice: per-tap [o][c=64] hi+lo, pitch 144 B (conflict-free ldsm),
// double-buffered, prefetched by producers one tap ahead.
// full[s] = bar 1+s, empty[s] = bar 4+s. 36 phases (9 taps x 4 quarters).
// ---------------------------------------------------------------------------
#define STG_HALF 12288                           // 256*48
#define STG      (2 * STG_HALF)
#define SM_W     (3 * STG)                       // 73728
#define WS_PITCH 144

// K2 (64 o)
#define WS2_HALF (OO * WS_PITCH)                 // 9216
#define WS2_BUF  (2 * WS2_HALF)                  // hi+lo = 18432
#define K2_SMEM  (SM_W + 2 * WS2_BUF)            // 110592

// K1 (32 o)
#define WS1_HALF (NOFF * WS_PITCH)               // 4608
#define WS1_BUF  (2 * WS1_HALF)                  // 9216
#define K1_SMEM  (SM_W + 2 * WS1_BUF)            // 92160

// Load one thread's share of a W slice (16 ch) for tap `tap` into dst buffer.
// idx in 0..255 -> o = idx>>2 (guard o<nrows), cq = (idx&3)*16.
__device__ __forceinline__ void wslice_load(char* dst_hi, char* dst_lo,
                                            const unsigned short* src,
                                            int plane_stride,
                                            int tap, int idx, int nrows)
{
    int o = idx >> 2;
    if (o < nrows) {
        int cq = (idx & 3) << 4;
        const uint4* sh = (const uint4*)(src + o * WPITCH + tap * 64 + cq);
        const uint4* sl = (const uint4*)(src + plane_stride + o * WPITCH + tap * 64 + cq);
        uint4* dh = (uint4*)(dst_hi + o * WS_PITCH + cq * 2);
        uint4* dl = (uint4*)(dst_lo + o * WS_PITCH + cq * 2);
        dh[0] = sh[0]; dh[1] = sh[1];
        dl[0] = sl[0]; dl[1] = sl[1];
    }
}

// ---------------------------------------------------------------------------
// Kernel 1: offset conv, warp-specialized im2col GEMM, W-sliced. N=32.
// ---------------------------------------------------------------------------
__global__ __launch_bounds__(512, 1)
void offset_mma_kernel(const float* __restrict__ feat,
                       const float* __restrict__ b_off)
{
    extern __shared__ char smc[];
    const uint32_t sb = smem_u32(smc);

    const int y0  = blockIdx.x * 2;
    const int b   = blockIdx.y;
    const int tid = threadIdx.x;
    const int warp = tid >> 5;
    const int lane = tid & 31;

    // load W slice for tap 0 into buffer 0 (threads 0..127 cover 32 o x 4 cq)
    wslice_load(smc + SM_W, smc + SM_W + WS1_HALF,
                g_w1, NOFF * WPITCH, 0, tid, NOFF);
    __syncthreads();

    if (warp >= 8) {
        // ---------------- producer ----------------
        const int ptid = (warp - 8) * 32 + lane;    // 0..255
        const int px   = ptid;
        const int yrow = y0 + (px >> 7);
        const int gx   = px & 127;
        const float* fb = feat + (size_t)b * CC * HWSZ;

        int s = 0;
        for (int p = 0; p < 36; p++) {
            const int tap = p >> 2;
            const int q   = p & 3;
            const int dy = tap / 3 - 1, dx = tap % 3 - 1;
            const int yy = yrow + dy, xx = gx + dx;
            const bool valid = (yy >= 0) && (yy < HH) && (xx >= 0) && (xx < WW);
            const float* fp = fb + (size_t)(q * 16) * HWSZ + yy * WW + xx;

            if (p >= 3) NBAR_SYNC(4 + s);

            // prefetch next tap's W slice (buffer (tap+1)&1) at q==3
            if (q == 3 && tap < 8) {
                char* wd = smc + SM_W + ((tap + 1) & 1) * WS1_BUF;
                wslice_load(wd, wd + WS1_HALF, g_w1, NOFF * WPITCH,
                            tap + 1, ptid, NOFF);
            }

            char* ahp = smc + s * STG + px * 48;
            char* alp = ahp + STG_HALF;
            uint2 hp[4], lp[4];
#pragma unroll
            for (int j = 0; j < 4; j++) {
                float v[4];
#pragma unroll
                for (int qq = 0; qq < 4; qq++)
                    v[qq] = valid ? __ldg(fp + (size_t)(4 * j + qq) * HWSZ) : 0.f;
                split_pack(v, hp[j], lp[j]);
            }
            *(uint4*)(ahp)      = make_uint4(hp[0].x, hp[0].y, hp[1].x, hp[1].y);
            *(uint4*)(ahp + 16) = make_uint4(hp[2].x, hp[2].y, hp[3].x, hp[3].y);
            *(uint4*)(alp)      = make_uint4(lp[0].x, lp[0].y, lp[1].x, lp[1].y);
            *(uint4*)(alp + 16) = make_uint4(lp[2].x, lp[2].y, lp[3].x, lp[3].y);

            NBAR_ARRIVE(1 + s);
            if (++s == 3) s = 0;
        }
    } else {
        // ---------------- consumer: 32 px x 32 o ----------------
        float acc[2][4][4];
#pragma unroll
        for (int t = 0; t < 2; t++)
#pragma unroll
            for (int ob = 0; ob < 4; ob++)
#pragma unroll
                for (int i = 0; i < 4; i++) acc[t][ob][i] = 0.f;

        const uint32_t aBase = sb
            + (uint32_t)(warp * 32 + (lane & 15)) * 48 + (uint32_t)((lane >> 4) * 16);
        const int bg  = lane >> 3;
        const int bl8 = lane & 7;
        const uint32_t b_row_off = ((bg >> 1) * 8 + bl8) * WS_PITCH;
        const uint32_t b_k8     = (bg & 1) * 16;

        int s = 0;
        for (int p = 0; p < 36; p++) {
            const int tap = p >> 2;
            const int q   = p & 3;
            NBAR_SYNC(1 + s);

            const uint32_t stoff = (uint32_t)(s * STG);
            uint32_t ah[2][4], al[2][4];
            ldsm4(ah[0], aBase + stoff);
            ldsm4(ah[1], aBase + stoff + 16 * 48);
            ldsm4(al[0], aBase + stoff + STG_HALF);
            ldsm4(al[1], aBase + stoff + STG_HALF + 16 * 48);
            if (p < 33) NBAR_ARRIVE(4 + s);

            const uint32_t wb = sb + SM_W + (uint32_t)((tap & 1) * WS1_BUF);
            const uint32_t bcol = (uint32_t)(q * 32) + b_k8;
            uint32_t bh[8], bl[8];
#pragma unroll
            for (int oi = 0; oi < 2; oi++) {
                uint32_t roff = (uint32_t)(oi * 16) * WS_PITCH + b_row_off + bcol;
                ldsm4(&bh[oi * 4], wb + roff);
                ldsm4(&bl[oi * 4], wb + WS1_HALF + roff);
            }
#pragma unroll
            for (int t = 0; t < 2; t++)
#pragma unroll
                for (int obl = 0; obl < 4; obl++) {
                    float* a = acc[t][obl];
                    mma_bf16(a, ah[t], &bh[obl * 2]);
                    mma_bf16(a, ah[t], &bl[obl * 2]);
                    mma_bf16(a, al[t], &bh[obl * 2]);
                }
            if (++s == 3) s = 0;
        }

        // epilogue: bias, store to g_om; only o < 27
#pragma unroll
        for (int t = 0; t < 2; t++) {
            const int prow = warp * 32 + t * 16 + (lane >> 2);
            const int row1 = y0 + (prow >> 7);
            const int x1   = prow & 127;
            const int prow2 = prow + 8;
            const int row2 = y0 + (prow2 >> 7);
            const int x2   = prow2 & 127;
#pragma unroll
            for (int ob = 0; ob < 4; ob++) {
                int o = ob * 8 + (lane & 3) * 2;
                if (o < 27) {
                    float bv = __ldg(b_off + o);
                    g_om[((b * 27 + o) * HH + row1) * WW + x1] = acc[t][ob][0] + bv;
                    g_om[((b * 27 + o) * HH + row2) * WW + x2] = acc[t][ob][2] + bv;
                }
                if (o + 1 < 27) {
                    float bv = __ldg(b_off + o + 1);
                    g_om[((b * 27 + o + 1) * HH + row1) * WW + x1] = acc[t][ob][1] + bv;
                    g_om[((b * 27 + o + 1) * HH + row2) * WW + x2] = acc[t][ob][3] + bv;
                }
            }
        }
    }
}

// ---------------------------------------------------------------------------
// Kernel 2: warp-specialized deform-GEMM, W-sliced (smem 108KB -> L1D alive).
// ---------------------------------------------------------------------------
__global__ __launch_bounds__(512, 1)
void deform_mma_kernel(const float* __restrict__ x,
                       const float* __restrict__ b_def,
                       float* __restrict__ out)
{
    extern __shared__ char smc[];
    const uint32_t sb = smem_u32(smc);

    const int y0  = blockIdx.x * 2;
    const int b   = blockIdx.y;
    const int tid = threadIdx.x;
    const int warp = tid >> 5;
    const int lane = tid & 31;

    // load W slice for tap 0 into buffer 0 (threads 0..255 cover 64 o x 4 cq)
    wslice_load(smc + SM_W, smc + SM_W + WS2_HALF,
                g_w2, OO * WPITCH, 0, tid, OO);
    __syncthreads();

    if (warp >= 8) {
        // ---------------- producer ----------------
        const int ptid = (warp - 8) * 32 + lane;
        const int px   = ptid;
        const int yrow = y0 + (px >> 7);
        const int gx   = px & 127;
        const float* xb = x + (size_t)b * CC * HWSZ;
        const int ombase = (b * 27 * HH + yrow) * WW + gx;

        float cw0, cw1, cw2, cw3;
        int   ci0, ci1, ci2, ci3;
        int s = 0;
        for (int p = 0; p < 36; p++) {
            const int tap = p >> 2;
            const int q   = p & 3;
            if (q == 0) {
                float offx = g_om[ombase + tap * HWSZ];
                float offy = g_om[ombase + (9 + tap) * HWSZ];
                float mz   = g_om[ombase + (18 + tap) * HWSZ];
                float m    = 1.f / (1.f + __expf(-mz));
                float ys = (float)(yrow + tap / 3 - 1) + offy;
                float xs = (float)(gx + tap % 3 - 1) + offx;
                float y0f = floorf(ys), x0f = floorf(xs);
                float wy1 = ys - y0f, wx1 = xs - x0f;
                int iy0 = (int)y0f, ix0 = (int)x0f;
                bool vy0 = (iy0 >= 0) && (iy0 < HH);
                bool vy1 = (iy0 + 1 >= 0) && (iy0 + 1 < HH);
                bool vx0 = (ix0 >= 0) && (ix0 < WW);
                bool vx1 = (ix0 + 1 >= 0) && (ix0 + 1 < WW);
                cw0 = (vy0 && vx0) ? (1.f - wy1) * (1.f - wx1) * m : 0.f;
                cw1 = (vy0 && vx1) ? (1.f - wy1) * wx1 * m : 0.f;
                cw2 = (vy1 && vx0) ? wy1 * (1.f - wx1) * m : 0.f;
                cw3 = (vy1 && vx1) ? wy1 * wx1 * m : 0.f;
                int y0c = min(max(iy0, 0), HH - 1);
                int y1c = min(max(iy0 + 1, 0), HH - 1);
                int x0c = min(max(ix0, 0), WW - 1);
                int x1c = min(max(ix0 + 1, 0), WW - 1);
                ci0 = y0c * WW + x0c;  ci1 = y0c * WW + x1c;
                ci2 = y1c * WW + x0c;  ci3 = y1c * WW + x1c;
            }
            if (p >= 3) NBAR_SYNC(4 + s);

            // prefetch next tap's W slice at q==3
            if (q == 3 && tap < 8) {
                char* wd = smc + SM_W + ((tap + 1) & 1) * WS2_BUF;
                wslice_load(wd, wd + WS2_HALF, g_w2, OO * WPITCH,
                            tap + 1, ptid, OO);
            }

            const float* xc0 = xb + (size_t)(q * 16) * HWSZ;
            char* ahp = smc + s * STG + px * 48;
            char* alp = ahp + STG_HALF;
            uint2 hp[4], lp[4];
#pragma unroll
            for (int j = 0; j < 4; j++) {
                float v[4];
#pragma unroll
                for (int qq = 0; qq < 4; qq++) {
                    const float* xc = xc0 + (size_t)(4 * j + qq) * HWSZ;
                    v[qq] = cw0 * __ldg(xc + ci0) + cw1 * __ldg(xc + ci1)
                          + cw2 * __ldg(xc + ci2) + cw3 * __ldg(xc + ci3);
                }
                split_pack(v, hp[j], lp[j]);
            }
            *(uint4*)(ahp)      = make_uint4(hp[0].x, hp[0].y, hp[1].x, hp[1].y);
            *(uint4*)(ahp + 16) = make_uint4(hp[2].x, hp[2].y, hp[3].x, hp[3].y);
            *(uint4*)(alp)      = make_uint4(lp[0].x, lp[0].y, lp[1].x, lp[1].y);
            *(uint4*)(alp + 16) = make_uint4(lp[2].x, lp[2].y, lp[3].x, lp[3].y);

            NBAR_ARRIVE(1 + s);
            if (++s == 3) s = 0;
        }
    } else {
        // ---------------- consumer ----------------
        float acc[2][8][4];
#pragma unroll
        for (int t = 0; t < 2; t++)
#pragma unroll
            for (int ob = 0; ob < 8; ob++)
#pragma unroll
                for (int i = 0; i < 4; i++) acc[t][ob][i] = 0.f;

        const uint32_t aBase = sb
            + (uint32_t)(warp * 32 + (lane & 15)) * 48 + (uint32_t)((lane >> 4) * 16);
        const int bg  = lane >> 3;
        const int bl8 = lane & 7;
        const uint32_t b_row_off = ((bg >> 1) * 8 + bl8) * WS_PITCH;
        const uint32_t b_k8     = (bg & 1) * 16;

        int s = 0;
        for (int p = 0; p < 36; p++) {
            const int tap = p >> 2;
            const int q   = p & 3;
            NBAR_SYNC(1 + s);

            const uint32_t stoff = (uint32_t)(s * STG);
            uint32_t ah[2][4], al[2][4];
            ldsm4(ah[0], aBase + stoff);
            ldsm4(ah[1], aBase + stoff + 16 * 48);
            ldsm4(al[0], aBase + stoff + STG_HALF);
            ldsm4(al[1], aBase + stoff + STG_HALF + 16 * 48);
            if (p < 33) NBAR_ARRIVE(4 + s);

            const uint32_t wb = sb + SM_W + (uint32_t)((tap & 1) * WS2_BUF);
            const uint32_t bcol = (uint32_t)(q * 32) + b_k8;
#pragma unroll
            for (int half = 0; half < 2; half++) {
                uint32_t bh[8], bl[8];
#pragma unroll
                for (int oi = 0; oi < 2; oi++) {
                    int obp = half * 2 + oi;
                    uint32_t roff = (uint32_t)(obp * 16) * WS_PITCH + b_row_off + bcol;
                    ldsm4(&bh[oi * 4], wb + roff);
                    ldsm4(&bl[oi * 4], wb + WS2_HALF + roff);
                }
#pragma unroll
                for (int t = 0; t < 2; t++)
#pragma unroll
                    for (int obl = 0; obl < 4; obl++) {
                        float* a = acc[t][half * 4 + obl];
                        mma_bf16(a, ah[t], &bh[obl * 2]);
                        mma_bf16(a, ah[t], &bl[obl * 2]);
                        mma_bf16(a, al[t], &bh[obl * 2]);
                    }
            }
            if (++s == 3) s = 0;
        }

        // epilogue: bias + relu
#pragma unroll
        for (int t = 0; t < 2; t++) {
            const int prow = warp * 32 + t * 16 + (lane >> 2);
            const int row1 = y0 + (prow >> 7);
            const int x1   = prow & 127;
            const int prow2 = prow + 8;
            const int row2 = y0 + (prow2 >> 7);
            const int x2   = prow2 & 127;
#pragma unroll
            for (int ob = 0; ob < 8; ob++) {
                int o = ob * 8 + (lane & 3) * 2;
                float b0v = __ldg(b_def + o);
                float b1v = __ldg(b_def + o + 1);
                float* p1 = out + (((size_t)(b * OO + o) * HH + row1) * WW + x1);
                float* p2 = out + (((size_t)(b * OO + o) * HH + row2) * WW + x2);
                p1[0]    = fmaxf(acc[t][ob][0] + b0v, 0.f);
                p1[HWSZ] = fmaxf(acc[t][ob][1] + b1v, 0.f);
                p2[0]    = fmaxf(acc[t][ob][2] + b0v, 0.f);
                p2[HWSZ] = fmaxf(acc[t][ob][3] + b1v, 0.f);
            }
        }
    }
}

// ---------------------------------------------------------------------------
extern "C" void kernel_launch(void* const* d_in, const int* in_sizes, int n_in,
                              void* d_out, int out_size)
{
    const float* x     = (const float*)d_in[0];
    const float* feat  = (const float*)d_in[1];
    const float* w_off = (const float*)d_in[2];
    const float* b_off = (const float*)d_in[3];
    const float* w_def = (const float*)d_in[4];
    const float* b_def = (const float*)d_in[5];
    float* out = (float*)d_out;

    cudaFuncSetAttribute(offset_mma_kernel,
                         cudaFuncAttributeMaxDynamicSharedMemorySize, K1_SMEM);
    cudaFuncSetAttribute(deform_mma_kernel,
                         cudaFuncAttributeMaxDynamicSharedMemorySize, K2_SMEM);

    dim3 gridp(OO + NOFF, 5);
    prep_w_kernel<<<gridp, 128>>>(w_def, w_off);
    dim3 grid1(HH / 2, BB);
    offset_mma_kernel<<<grid1, 512, K1_SMEM>>>(feat, b_off);
    dim3 grid2(HH / 2, BB);
    deform_mma_kernel<<<grid2, 512, K2_SMEM>>>(x, b_def, out);
}

// round 14
// speedup vs baseline: 1.6192x; 1.0578x over previous
#include <cuda_runtime.h>
#include <cuda_bf16.h>
#include <math.h>
#include <stdint.h>

// Problem constants (fixed by setup_inputs)
#define BB   4
#define CC   64
#define OO   64
#define HH   128
#define WW   128
#define HWSZ (HH * WW)

// Scratch: offset-conv output; split weights (def: 64 o, off: 32 o padded)
#define WPITCH 584
#define NOFF   32
__device__ float g_om[BB * 27 * HWSZ];
__device__ unsigned short g_w2[2 * OO * WPITCH];     // w_def hi | lo
__device__ unsigned short g_w1[2 * NOFF * WPITCH];   // w_off hi | lo (o>=27 zero)

__device__ __forceinline__ uint32_t smem_u32(const void* p) {
    uint32_t a;
    asm("{ .reg .u64 t; cvta.to.shared.u64 t, %1; cvt.u32.u64 %0, t; }"
        : "=r"(a) : "l"(p));
    return a;
}
__device__ __forceinline__ void ldsm4(uint32_t* r, uint32_t addr) {
    asm volatile("ldmatrix.sync.aligned.m8n8.x4.shared.b16 {%0,%1,%2,%3}, [%4];"
        : "=r"(r[0]), "=r"(r[1]), "=r"(r[2]), "=r"(r[3]) : "r"(addr));
}
__device__ __forceinline__ void mma_bf16(float* d, const uint32_t* a, const uint32_t* b) {
    asm volatile(
        "mma.sync.aligned.m16n8k16.row.col.f32.bf16.bf16.f32 "
        "{%0,%1,%2,%3}, {%4,%5,%6,%7}, {%8,%9}, {%0,%1,%2,%3};"
        : "+f"(d[0]), "+f"(d[1]), "+f"(d[2]), "+f"(d[3])
        : "r"(a[0]), "r"(a[1]), "r"(a[2]), "r"(a[3]), "r"(b[0]), "r"(b[1]));
}
__device__ __forceinline__ void split_pack(const float* v, uint2& hp, uint2& lp) {
    unsigned short h[4], l[4];
#pragma unroll
    for (int q = 0; q < 4; q++) {
        __nv_bfloat16 hb = __float2bfloat16(v[q]);
        __nv_bfloat16 lb = __float2bfloat16(v[q] - __bfloat162float(hb));
        h[q] = __bfloat16_as_ushort(hb);
        l[q] = __bfloat16_as_ushort(lb);
    }
    hp.x = ((uint32_t)h[1] << 16) | h[0];
    hp.y = ((uint32_t)h[3] << 16) | h[2];
    lp.x = ((uint32_t)l[1] << 16) | l[0];
    lp.y = ((uint32_t)l[3] << 16) | l[2];
}

// named barriers: 256 = 128 sync-side + 128 arrive-side (per CTA)
#define NBAR_SYNC(id)   asm volatile("bar.sync %0, 256;"   :: "r"(id) : "memory")
#define NBAR_ARRIVE(id) asm volatile("bar.arrive %0, 256;" :: "r"(id) : "memory")

// ---------------------------------------------------------------------------
// Prep: split w_def (blocks 0..63) and w_off (blocks 64..95) into bf16 hi/lo.
// ---------------------------------------------------------------------------
__global__ void prep_w_kernel(const float* __restrict__ w_def,
                              const float* __restrict__ w_off)
{
    int ob  = blockIdx.x;
    int col = blockIdx.y * 128 + threadIdx.x;
    if (col >= WPITCH) return;
    float w = 0.f;
    if (col < 576) {
        int tap = col >> 6, c = col & 63;
        if (ob < OO) w = w_def[(ob * CC + c) * 9 + tap];
        else if (ob - OO < 27) w = w_off[((ob - OO) * CC + c) * 9 + tap];
    }
    __nv_bfloat16 hb = __float2bfloat16(w);
    __nv_bfloat16 lb = __float2bfloat16(w - __bfloat162float(hb));
    if (ob < OO) {
        g_w2[ob * WPITCH + col] = __bfloat16_as_ushort(hb);
        g_w2[OO * WPITCH + ob * WPITCH + col] = __bfloat16_as_ushort(lb);
    } else {
        int o = ob - OO;
        g_w1[o * WPITCH + col] = __bfloat16_as_ushort(hb);
        g_w1[NOFF * WPITCH + o * WPITCH + col] = __bfloat16_as_ushort(lb);
    }
}

// ---------------------------------------------------------------------------
// Shared geometry (1-row CTAs, 128 px, 256 threads, 2 CTAs/SM).
// Ring: 3 stages x (128 px x 16 ch, hi+lo), pitch 48 B, at smem offset 0.
// W slice: per-tap [o][c=64] hi+lo, pitch 144 B, double-buffered,
// prefetched by producers one tap ahead.
// full[s] = bar 1+s, empty[s] = bar 4+s. 36 phases (9 taps x 4 quarters).
// ---------------------------------------------------------------------------
#define STG_HALF 6144                            // 128*48
#define STG      (2 * STG_HALF)
#define SM_W     (3 * STG)                       // 36864
#define WS_PITCH 144

// K2 (64 o)
#define WS2_HALF (OO * WS_PITCH)                 // 9216
#define WS2_BUF  (2 * WS2_HALF)                  // 18432
#define K2_SMEM  (SM_W + 2 * WS2_BUF)            // 73728

// K1 (32 o)
#define WS1_HALF (NOFF * WS_PITCH)               // 4608
#define WS1_BUF  (2 * WS1_HALF)                  // 9216
#define K1_SMEM  (SM_W + 2 * WS1_BUF)            // 55296

// Load one thread's share of a W slice (16 ch) for tap `tap` into dst buffer.
// idx -> o = idx>>2 (guard o<nrows), cq = (idx&3)*16.
__device__ __forceinline__ void wslice_load(char* dst_hi, char* dst_lo,
                                            const unsigned short* src,
                                            int plane_stride,
                                            int tap, int idx, int nrows)
{
    int o = idx >> 2;
    if (o < nrows) {
        int cq = (idx & 3) << 4;
        const uint4* sh = (const uint4*)(src + o * WPITCH + tap * 64 + cq);
        const uint4* sl = (const uint4*)(src + plane_stride + o * WPITCH + tap * 64 + cq);
        uint4* dh = (uint4*)(dst_hi + o * WS_PITCH + cq * 2);
        uint4* dl = (uint4*)(dst_lo + o * WS_PITCH + cq * 2);
        dh[0] = sh[0]; dh[1] = sh[1];
        dl[0] = sl[0]; dl[1] = sl[1];
    }
}

// ---------------------------------------------------------------------------
// Kernel 1: offset conv, warp-specialized im2col GEMM, 1 row/CTA. N=32.
// warps 0-3 consumers, 4-7 producers.
// ---------------------------------------------------------------------------
__global__ __launch_bounds__(256, 2)
void offset_mma_kernel(const float* __restrict__ feat,
                       const float* __restrict__ b_off)
{
    extern __shared__ char smc[];
    const uint32_t sb = smem_u32(smc);

    const int y    = blockIdx.x;
    const int b    = blockIdx.y;
    const int tid  = threadIdx.x;
    const int warp = tid >> 5;
    const int lane = tid & 31;

    // load W slice for tap 0 into buffer 0 (tid 0..127 cover 32 o x 4 cq)
    wslice_load(smc + SM_W, smc + SM_W + WS1_HALF,
                g_w1, NOFF * WPITCH, 0, tid, NOFF);
    __syncthreads();

    if (warp >= 4) {
        // ---------------- producer: coalesced shifted feat reads ----------
        const int ptid = (warp - 4) * 32 + lane;    // 0..127 = px
        const int px   = ptid;
        const float* fb = feat + (size_t)b * CC * HWSZ;

        int s = 0;
        for (int p = 0; p < 36; p++) {
            const int tap = p >> 2;
            const int q   = p & 3;
            const int dy = tap / 3 - 1, dx = tap % 3 - 1;
            const int yy = y + dy, xx = px + dx;
            const bool valid = (yy >= 0) && (yy < HH) && (xx >= 0) && (xx < WW);
            const float* fp = fb + (size_t)(q * 16) * HWSZ + yy * WW + xx;

            if (p >= 3) NBAR_SYNC(4 + s);

            if (q == 3 && tap < 8) {
                char* wd = smc + SM_W + ((tap + 1) & 1) * WS1_BUF;
                wslice_load(wd, wd + WS1_HALF, g_w1, NOFF * WPITCH,
                            tap + 1, ptid, NOFF);
            }

            char* ahp = smc + s * STG + px * 48;
            char* alp = ahp + STG_HALF;
            uint2 hp[4], lp[4];
#pragma unroll
            for (int j = 0; j < 4; j++) {
                float v[4];
#pragma unroll
                for (int qq = 0; qq < 4; qq++)
                    v[qq] = valid ? __ldg(fp + (size_t)(4 * j + qq) * HWSZ) : 0.f;
                split_pack(v, hp[j], lp[j]);
            }
            *(uint4*)(ahp)      = make_uint4(hp[0].x, hp[0].y, hp[1].x, hp[1].y);
            *(uint4*)(ahp + 16) = make_uint4(hp[2].x, hp[2].y, hp[3].x, hp[3].y);
            *(uint4*)(alp)      = make_uint4(lp[0].x, lp[0].y, lp[1].x, lp[1].y);
            *(uint4*)(alp + 16) = make_uint4(lp[2].x, lp[2].y, lp[3].x, lp[3].y);

            NBAR_ARRIVE(1 + s);
            if (++s == 3) s = 0;
        }
    } else {
        // ---------------- consumer: 32 px x 32 o per warp ----------------
        float acc[2][4][4];
#pragma unroll
        for (int t = 0; t < 2; t++)
#pragma unroll
            for (int ob = 0; ob < 4; ob++)
#pragma unroll
                for (int i = 0; i < 4; i++) acc[t][ob][i] = 0.f;

        const uint32_t aBase = sb
            + (uint32_t)(warp * 32 + (lane & 15)) * 48 + (uint32_t)((lane >> 4) * 16);
        const int bg  = lane >> 3;
        const int bl8 = lane & 7;
        const uint32_t b_row_off = ((bg >> 1) * 8 + bl8) * WS_PITCH;
        const uint32_t b_k8     = (bg & 1) * 16;

        int s = 0;
        for (int p = 0; p < 36; p++) {
            const int tap = p >> 2;
            const int q   = p & 3;
            NBAR_SYNC(1 + s);

            const uint32_t stoff = (uint32_t)(s * STG);
            uint32_t ah[2][4], al[2][4];
            ldsm4(ah[0], aBase + stoff);
            ldsm4(ah[1], aBase + stoff + 16 * 48);
            ldsm4(al[0], aBase + stoff + STG_HALF);
            ldsm4(al[1], aBase + stoff + STG_HALF + 16 * 48);
            if (p < 33) NBAR_ARRIVE(4 + s);

            const uint32_t wb = sb + SM_W + (uint32_t)((tap & 1) * WS1_BUF);
            const uint32_t bcol = (uint32_t)(q * 32) + b_k8;
            uint32_t bh[8], bl[8];
#pragma unroll
            for (int oi = 0; oi < 2; oi++) {
                uint32_t roff = (uint32_t)(oi * 16) * WS_PITCH + b_row_off + bcol;
                ldsm4(&bh[oi * 4], wb + roff);
                ldsm4(&bl[oi * 4], wb + WS1_HALF + roff);
            }
#pragma unroll
            for (int t = 0; t < 2; t++)
#pragma unroll
                for (int obl = 0; obl < 4; obl++) {
                    float* a = acc[t][obl];
                    mma_bf16(a, ah[t], &bh[obl * 2]);
                    mma_bf16(a, ah[t], &bl[obl * 2]);
                    mma_bf16(a, al[t], &bh[obl * 2]);
                }
            if (++s == 3) s = 0;
        }

        // epilogue: bias, store to g_om; only o < 27
#pragma unroll
        for (int t = 0; t < 2; t++) {
            const int x1 = warp * 32 + t * 16 + (lane >> 2);
            const int x2 = x1 + 8;
#pragma unroll
            for (int ob = 0; ob < 4; ob++) {
                int o = ob * 8 + (lane & 3) * 2;
                if (o < 27) {
                    float bv = __ldg(b_off + o);
                    g_om[((b * 27 + o) * HH + y) * WW + x1] = acc[t][ob][0] + bv;
                    g_om[((b * 27 + o) * HH + y) * WW + x2] = acc[t][ob][2] + bv;
                }
                if (o + 1 < 27) {
                    float bv = __ldg(b_off + o + 1);
                    g_om[((b * 27 + o + 1) * HH + y) * WW + x1] = acc[t][ob][1] + bv;
                    g_om[((b * 27 + o + 1) * HH + y) * WW + x2] = acc[t][ob][3] + bv;
                }
            }
        }
    }
}

// ---------------------------------------------------------------------------
// Kernel 2: warp-specialized deform-GEMM, 1 row/CTA, 2 CTAs/SM.
// warps 0-3 consumers, 4-7 producers.
// ---------------------------------------------------------------------------
__global__ __launch_bounds__(256, 2)
void deform_mma_kernel(const float* __restrict__ x,
                       const float* __restrict__ b_def,
                       float* __restrict__ out)
{
    extern __shared__ char smc[];
    const uint32_t sb = smem_u32(smc);

    const int y    = blockIdx.x;
    const int b    = blockIdx.y;
    const int tid  = threadIdx.x;
    const int warp = tid >> 5;
    const int lane = tid & 31;

    // load W slice for tap 0 into buffer 0 (tid 0..255 cover 64 o x 4 cq)
    wslice_load(smc + SM_W, smc + SM_W + WS2_HALF,
                g_w2, OO * WPITCH, 0, tid, OO);
    __syncthreads();

    if (warp >= 4) {
        // ---------------- producer ----------------
        const int ptid = (warp - 4) * 32 + lane;    // 0..127 = px
        const int px   = ptid;
        const float* xb = x + (size_t)b * CC * HWSZ;
        const int ombase = (b * 27 * HH + y) * WW + px;

        float cw0, cw1, cw2, cw3;
        int   ci0, ci1, ci2, ci3;
        int s = 0;
        for (int p = 0; p < 36; p++) {
            const int tap = p >> 2;
            const int q   = p & 3;
            if (q == 0) {
                float offx = g_om[ombase + tap * HWSZ];
                float offy = g_om[ombase + (9 + tap) * HWSZ];
                float mz   = g_om[ombase + (18 + tap) * HWSZ];
                float m    = 1.f / (1.f + __expf(-mz));
                float ys = (float)(y + tap / 3 - 1) + offy;
                float xs = (float)(px + tap % 3 - 1) + offx;
                float y0f = floorf(ys), x0f = floorf(xs);
                float wy1 = ys - y0f, wx1 = xs - x0f;
                int iy0 = (int)y0f, ix0 = (int)x0f;
                bool vy0 = (iy0 >= 0) && (iy0 < HH);
                bool vy1 = (iy0 + 1 >= 0) && (iy0 + 1 < HH);
                bool vx0 = (ix0 >= 0) && (ix0 < WW);
                bool vx1 = (ix0 + 1 >= 0) && (ix0 + 1 < WW);
                cw0 = (vy0 && vx0) ? (1.f - wy1) * (1.f - wx1) * m : 0.f;
                cw1 = (vy0 && vx1) ? (1.f - wy1) * wx1 * m : 0.f;
                cw2 = (vy1 && vx0) ? wy1 * (1.f - wx1) * m : 0.f;
                cw3 = (vy1 && vx1) ? wy1 * wx1 * m : 0.f;
                int y0c = min(max(iy0, 0), HH - 1);
                int y1c = min(max(iy0 + 1, 0), HH - 1);
                int x0c = min(max(ix0, 0), WW - 1);
                int x1c = min(max(ix0 + 1, 0), WW - 1);
                ci0 = y0c * WW + x0c;  ci1 = y0c * WW + x1c;
                ci2 = y1c * WW + x0c;  ci3 = y1c * WW + x1c;
            }
            if (p >= 3) NBAR_SYNC(4 + s);

            // prefetch next tap's W slice (two halves: 128 threads, 64 o)
            if (q == 3 && tap < 8) {
                char* wd = smc + SM_W + ((tap + 1) & 1) * WS2_BUF;
                wslice_load(wd, wd + WS2_HALF, g_w2, OO * WPITCH,
                            tap + 1, ptid, OO);
                wslice_load(wd, wd + WS2_HALF, g_w2, OO * WPITCH,
                            tap + 1, ptid + 128, OO);
            }

            const float* xc0 = xb + (size_t)(q * 16) * HWSZ;
            char* ahp = smc + s * STG + px * 48;
            char* alp = ahp + STG_HALF;
            uint2 hp[4], lp[4];
#pragma unroll
            for (int j = 0; j < 4; j++) {
                float v[4];
#pragma unroll
                for (int qq = 0; qq < 4; qq++) {
                    const float* xc = xc0 + (size_t)(4 * j + qq) * HWSZ;
                    v[qq] = cw0 * __ldg(xc + ci0) + cw1 * __ldg(xc + ci1)
                          + cw2 * __ldg(xc + ci2) + cw3 * __ldg(xc + ci3);
                }
                split_pack(v, hp[j], lp[j]);
            }
            *(uint4*)(ahp)      = make_uint4(hp[0].x, hp[0].y, hp[1].x, hp[1].y);
            *(uint4*)(ahp + 16) = make_uint4(hp[2].x, hp[2].y, hp[3].x, hp[3].y);
            *(uint4*)(alp)      = make_uint4(lp[0].x, lp[0].y, lp[1].x, lp[1].y);
            *(uint4*)(alp + 16) = make_uint4(lp[2].x, lp[2].y, lp[3].x, lp[3].y);

            NBAR_ARRIVE(1 + s);
            if (++s == 3) s = 0;
        }
    } else {
        // ---------------- consumer: 32 px x 64 o per warp ----------------
        float acc[2][8][4];
#pragma unroll
        for (int t = 0; t < 2; t++)
#pragma unroll
            for (int ob = 0; ob < 8; ob++)
#pragma unroll
                for (int i = 0; i < 4; i++) acc[t][ob][i] = 0.f;

        const uint32_t aBase = sb
            + (uint32_t)(warp * 32 + (lane & 15)) * 48 + (uint32_t)((lane >> 4) * 16);
        const int bg  = lane >> 3;
        const int bl8 = lane & 7;
        const uint32_t b_row_off = ((bg >> 1) * 8 + bl8) * WS_PITCH;
        const uint32_t b_k8     = (bg & 1) * 16;

        int s = 0;
        for (int p = 0; p < 36; p++) {
            const int tap = p >> 2;
            const int q   = p & 3;
            NBAR_SYNC(1 + s);

            const uint32_t stoff = (uint32_t)(s * STG);
            uint32_t ah[2][4], al[2][4];
            ldsm4(ah[0], aBase + stoff);
            ldsm4(ah[1], aBase + stoff + 16 * 48);
            ldsm4(al[0], aBase + stoff + STG_HALF);
            ldsm4(al[1], aBase + stoff + STG_HALF + 16 * 48);
            if (p < 33) NBAR_ARRIVE(4 + s);

            const uint32_t wb = sb + SM_W + (uint32_t)((tap & 1) * WS2_BUF);
            const uint32_t bcol = (uint32_t)(q * 32) + b_k8;
#pragma unroll
            for (int half = 0; half < 2; half++) {
                uint32_t bh[8], bl[8];
#pragma unroll
                for (int oi = 0; oi < 2; oi++) {
                    int obp = half * 2 + oi;
                    uint32_t roff = (uint32_t)(obp * 16) * WS_PITCH + b_row_off + bcol;
                    ldsm4(&bh[oi * 4], wb + roff);
                    ldsm4(&bl[oi * 4], wb + WS2_HALF + roff);
                }
#pragma unroll
                for (int t = 0; t < 2; t++)
#pragma unroll
                    for (int obl = 0; obl < 4; obl++) {
                        float* a = acc[t][half * 4 + obl];
                        mma_bf16(a, ah[t], &bh[obl * 2]);
                        mma_bf16(a, ah[t], &bl[obl * 2]);
                        mma_bf16(a, al[t], &bh[obl * 2]);
                    }
            }
            if (++s == 3) s = 0;
        }

        // epilogue: bias + relu
#pragma unroll
        for (int t = 0; t < 2; t++) {
            const int x1 = warp * 32 + t * 16 + (lane >> 2);
            const int x2 = x1 + 8;
#pragma unroll
            for (int ob = 0; ob < 8; ob++) {
                int o = ob * 8 + (lane & 3) * 2;
                float b0v = __ldg(b_def + o);
                float b1v = __ldg(b_def + o + 1);
                float* p1 = out + (((size_t)(b * OO + o) * HH + y) * WW + x1);
                float* p2 = out + (((size_t)(b * OO + o) * HH + y) * WW + x2);
                p1[0]    = fmaxf(acc[t][ob][0] + b0v, 0.f);
                p1[HWSZ] = fmaxf(acc[t][ob][1] + b1v, 0.f);
                p2[0]    = fmaxf(acc[t][ob][2] + b0v, 0.f);
                p2[HWSZ] = fmaxf(acc[t][ob][3] + b1v, 0.f);
            }
        }
    }
}

// ---------------------------------------------------------------------------
extern "C" void kernel_launch(void* const* d_in, const int* in_sizes, int n_in,
                              void* d_out, int out_size)
{
    const float* x     = (const float*)d_in[0];
    const float* feat  = (const float*)d_in[1];
    const float* w_off = (const float*)d_in[2];
    const float* b_off = (const float*)d_in[3];
    const float* w_def = (const float*)d_in[4];
    const float* b_def = (const float*)d_in[5];
    float* out = (float*)d_out;

    cudaFuncSetAttribute(offset_mma_kernel,
                         cudaFuncAttributeMaxDynamicSharedMemorySize, K1_SMEM);
    cudaFuncSetAttribute(deform_mma_kernel,
                         cudaFuncAttributeMaxDynamicSharedMemorySize, K2_SMEM);

    dim3 gridp(OO + NOFF, 5);
    prep_w_kernel<<<gridp, 128>>>(w_def, w_off);
    dim3 grid1(HH, BB);
    offset_mma_kernel<<<grid1, 256, K1_SMEM>>>(feat, b_off);
    dim3 grid2(HH, BB);
    deform_mma_kernel<<<grid2, 256, K2_SMEM>>>(x, b_def, out);
}

// round 16
// speedup vs baseline: 1.6409x; 1.0134x over previous
#include <cuda_runtime.h>
#include <cuda_bf16.h>
#include <math.h>
#include <stdint.h>

// Problem constants (fixed by setup_inputs)
#define BB   4
#define CC   64
#define OO   64
#define HH   128
#define WW   128
#define HWSZ (HH * WW)

// Split weights (def: 64 o, off: 32 o padded)
#define WPITCH 584
#define NOFF   32
__device__ unsigned short g_w2[2 * OO * WPITCH];     // w_def hi | lo
__device__ unsigned short g_w1[2 * NOFF * WPITCH];   // w_off hi | lo (o>=27 zero)

__device__ __forceinline__ uint32_t smem_u32(const void* p) {
    uint32_t a;
    asm("{ .reg .u64 t; cvta.to.shared.u64 t, %1; cvt.u32.u64 %0, t; }"
        : "=r"(a) : "l"(p));
    return a;
}
__device__ __forceinline__ void ldsm4(uint32_t* r, uint32_t addr) {
    asm volatile("ldmatrix.sync.aligned.m8n8.x4.shared.b16 {%0,%1,%2,%3}, [%4];"
        : "=r"(r[0]), "=r"(r[1]), "=r"(r[2]), "=r"(r[3]) : "r"(addr));
}
__device__ __forceinline__ void mma_bf16(float* d, const uint32_t* a, const uint32_t* b) {
    asm volatile(
        "mma.sync.aligned.m16n8k16.row.col.f32.bf16.bf16.f32 "
        "{%0,%1,%2,%3}, {%4,%5,%6,%7}, {%8,%9}, {%0,%1,%2,%3};"
        : "+f"(d[0]), "+f"(d[1]), "+f"(d[2]), "+f"(d[3])
        : "r"(a[0]), "r"(a[1]), "r"(a[2]), "r"(a[3]), "r"(b[0]), "r"(b[1]));
}
__device__ __forceinline__ void split_pack(const float* v, uint2& hp, uint2& lp) {
    unsigned short h[4], l[4];
#pragma unroll
    for (int q = 0; q < 4; q++) {
        __nv_bfloat16 hb = __float2bfloat16(v[q]);
        __nv_bfloat16 lb = __float2bfloat16(v[q] - __bfloat162float(hb));
        h[q] = __bfloat16_as_ushort(hb);
        l[q] = __bfloat16_as_ushort(lb);
    }
    hp.x = ((uint32_t)h[1] << 16) | h[0];
    hp.y = ((uint32_t)h[3] << 16) | h[2];
    lp.x = ((uint32_t)l[1] << 16) | l[0];
    lp.y = ((uint32_t)l[3] << 16) | l[2];
}

// named barriers: 256 = 128 sync-side + 128 arrive-side (per CTA)
#define NBAR_SYNC(id)   asm volatile("bar.sync %0, 256;"   :: "r"(id) : "memory")
#define NBAR_ARRIVE(id) asm volatile("bar.arrive %0, 256;" :: "r"(id) : "memory")

// ---------------------------------------------------------------------------
// Prep: split w_def (blocks 0..63) and w_off (blocks 64..95) into bf16 hi/lo.
// ---------------------------------------------------------------------------
__global__ void prep_w_kernel(const float* __restrict__ w_def,
                              const float* __restrict__ w_off)
{
    int ob  = blockIdx.x;
    int col = blockIdx.y * 128 + threadIdx.x;
    if (col >= WPITCH) return;
    float w = 0.f;
    if (col < 576) {
        int tap = col >> 6, c = col & 63;
        if (ob < OO) w = w_def[(ob * CC + c) * 9 + tap];
        else if (ob - OO < 27) w = w_off[((ob - OO) * CC + c) * 9 + tap];
    }
    __nv_bfloat16 hb = __float2bfloat16(w);
    __nv_bfloat16 lb = __float2bfloat16(w - __bfloat162float(hb));
    if (ob < OO) {
        g_w2[ob * WPITCH + col] = __bfloat16_as_ushort(hb);
        g_w2[OO * WPITCH + ob * WPITCH + col] = __bfloat16_as_ushort(lb);
    } else {
        int o = ob - OO;
        g_w1[o * WPITCH + col] = __bfloat16_as_ushort(hb);
        g_w1[NOFF * WPITCH + o * WPITCH + col] = __bfloat16_as_ushort(lb);
    }
}

// ---------------------------------------------------------------------------
// Fused geometry (1-row CTAs, 128 px, 256 threads, 2 CTAs/SM).
// Ring: 3 stages x (128 px x 16 ch, hi+lo), pitch 48 B, offset 0.
// W region: double-buffered per-tap slice (sized for K2's 64 o).
// om: [27(pad 32 rows unused)][128] fp32 in smem.
// full[s] = bar 1+s, empty[s] = bar 4+s. 36 phases per half.
// ---------------------------------------------------------------------------
#define STG_HALF 6144                            // 128*48
#define STG      (2 * STG_HALF)
#define SM_W     (3 * STG)                       // 36864
#define WS_PITCH 144

#define WS2_HALF (OO * WS_PITCH)                 // 9216
#define WS2_BUF  (2 * WS2_HALF)                  // 18432
#define WS1_HALF (NOFF * WS_PITCH)               // 4608
#define WS1_BUF  (2 * WS1_HALF)                  // 9216

#define SM_OM    (SM_W + 2 * WS2_BUF)            // 73728
#define F_SMEM   (SM_OM + 27 * 128 * 4)          // 87552

__device__ __forceinline__ void wslice_load(char* dst_hi, char* dst_lo,
                                            const unsigned short* src,
                                            int plane_stride,
                                            int tap, int idx, int nrows)
{
    int o = idx >> 2;
    if (o < nrows) {
        int cq = (idx & 3) << 4;
        const uint4* sh = (const uint4*)(src + o * WPITCH + tap * 64 + cq);
        const uint4* sl = (const uint4*)(src + plane_stride + o * WPITCH + tap * 64 + cq);
        uint4* dh = (uint4*)(dst_hi + o * WS_PITCH + cq * 2);
        uint4* dl = (uint4*)(dst_lo + o * WS_PITCH + cq * 2);
        dh[0] = sh[0]; dh[1] = sh[1];
        dl[0] = sl[0]; dl[1] = sl[1];
    }
}

// ---------------------------------------------------------------------------
// Fused kernel: per (b, y) row — offset conv (phase 1) then deform (phase 2).
// warps 0-3 consumers, 4-7 producers.
// ---------------------------------------------------------------------------
__global__ __launch_bounds__(256, 2)
void fused_dcn_kernel(const float* __restrict__ feat,
                      const float* __restrict__ x,
                      const float* __restrict__ b_off,
                      const float* __restrict__ b_def,
                      float* __restrict__ out)
{
    extern __shared__ char smc[];
    const uint32_t sb = smem_u32(smc);
    float* om_s = (float*)(smc + SM_OM);

    const int y    = blockIdx.x;
    const int b    = blockIdx.y;
    const int tid  = threadIdx.x;
    const int warp = tid >> 5;
    const int lane = tid & 31;

    // common ldsm addressing
    const uint32_t aBase = sb
        + (uint32_t)(warp * 32 + (lane & 15)) * 48 + (uint32_t)((lane >> 4) * 16);
    const int bg  = lane >> 3;
    const int bl8 = lane & 7;
    const uint32_t b_row_off = ((bg >> 1) * 8 + bl8) * WS_PITCH;
    const uint32_t b_k8     = (bg & 1) * 16;

    // ---- load W slice for K1 tap 0 into buffer 0 ----
    wslice_load(smc + SM_W, smc + SM_W + WS1_HALF,
                g_w1, NOFF * WPITCH, 0, tid, NOFF);
    __syncthreads();

    // =========================== PHASE 1: offset conv ======================
    if (warp >= 4) {
        // producer: coalesced shifted feat reads
        const int px = (warp - 4) * 32 + lane;
        const float* fb = feat + (size_t)b * CC * HWSZ;

        int s = 0;
        for (int p = 0; p < 36; p++) {
            const int tap = p >> 2;
            const int q   = p & 3;
            const int dy = tap / 3 - 1, dx = tap % 3 - 1;
            const int yy = y + dy, xx = px + dx;
            const bool valid = (yy >= 0) && (yy < HH) && (xx >= 0) && (xx < WW);
            const float* fp = fb + (size_t)(q * 16) * HWSZ + yy * WW + xx;

            if (p >= 3) NBAR_SYNC(4 + s);

            if (q == 3 && tap < 8) {
                char* wd = smc + SM_W + ((tap + 1) & 1) * WS1_BUF;
                wslice_load(wd, wd + WS1_HALF, g_w1, NOFF * WPITCH,
                            tap + 1, px, NOFF);
            }

            char* ahp = smc + s * STG + px * 48;
            char* alp = ahp + STG_HALF;
            uint2 hp[4], lp[4];
#pragma unroll
            for (int j = 0; j < 4; j++) {
                float v[4];
#pragma unroll
                for (int qq = 0; qq < 4; qq++)
                    v[qq] = valid ? __ldg(fp + (size_t)(4 * j + qq) * HWSZ) : 0.f;
                split_pack(v, hp[j], lp[j]);
            }
            *(uint4*)(ahp)      = make_uint4(hp[0].x, hp[0].y, hp[1].x, hp[1].y);
            *(uint4*)(ahp + 16) = make_uint4(hp[2].x, hp[2].y, hp[3].x, hp[3].y);
            *(uint4*)(alp)      = make_uint4(lp[0].x, lp[0].y, lp[1].x, lp[1].y);
            *(uint4*)(alp + 16) = make_uint4(lp[2].x, lp[2].y, lp[3].x, lp[3].y);

            NBAR_ARRIVE(1 + s);
            if (++s == 3) s = 0;
        }
    } else {
        // consumer: 32 px x 32 o per warp
        float acc[2][4][4];
#pragma unroll
        for (int t = 0; t < 2; t++)
#pragma unroll
            for (int ob = 0; ob < 4; ob++)
#pragma unroll
                for (int i = 0; i < 4; i++) acc[t][ob][i] = 0.f;

        int s = 0;
        for (int p = 0; p < 36; p++) {
            const int tap = p >> 2;
            const int q   = p & 3;
            NBAR_SYNC(1 + s);

            const uint32_t stoff = (uint32_t)(s * STG);
            uint32_t ah[2][4], al[2][4];
            ldsm4(ah[0], aBase + stoff);
            ldsm4(ah[1], aBase + stoff + 16 * 48);
            ldsm4(al[0], aBase + stoff + STG_HALF);
            ldsm4(al[1], aBase + stoff + STG_HALF + 16 * 48);
            if (p < 33) NBAR_ARRIVE(4 + s);

            const uint32_t wb = sb + SM_W + (uint32_t)((tap & 1) * WS1_BUF);
            const uint32_t bcol = (uint32_t)(q * 32) + b_k8;
            uint32_t bh[8], bl[8];
#pragma unroll
            for (int oi = 0; oi < 2; oi++) {
                uint32_t roff = (uint32_t)(oi * 16) * WS_PITCH + b_row_off + bcol;
                ldsm4(&bh[oi * 4], wb + roff);
                ldsm4(&bl[oi * 4], wb + WS1_HALF + roff);
            }
#pragma unroll
            for (int t = 0; t < 2; t++)
#pragma unroll
                for (int obl = 0; obl < 4; obl++) {
                    float* a = acc[t][obl];
                    mma_bf16(a, ah[t], &bh[obl * 2]);
                    mma_bf16(a, ah[t], &bl[obl * 2]);
                    mma_bf16(a, al[t], &bh[obl * 2]);
                }
            if (++s == 3) s = 0;
        }

        // epilogue: bias, store om to SMEM; only o < 27
#pragma unroll
        for (int t = 0; t < 2; t++) {
            const int x1 = warp * 32 + t * 16 + (lane >> 2);
            const int x2 = x1 + 8;
#pragma unroll
            for (int ob = 0; ob < 4; ob++) {
                int o = ob * 8 + (lane & 3) * 2;
                if (o < 27) {
                    float bv = __ldg(b_off + o);
                    om_s[o * 128 + x1] = acc[t][ob][0] + bv;
                    om_s[o * 128 + x2] = acc[t][ob][2] + bv;
                }
                if (o + 1 < 27) {
                    float bv = __ldg(b_off + o + 1);
                    om_s[(o + 1) * 128 + x1] = acc[t][ob][1] + bv;
                    om_s[(o + 1) * 128 + x2] = acc[t][ob][3] + bv;
                }
            }
        }
    }

    // ---- hand-off: om visible to all; load K2 tap-0 W slice ----
    __syncthreads();
    wslice_load(smc + SM_W, smc + SM_W + WS2_HALF,
                g_w2, OO * WPITCH, 0, tid, OO);
    __syncthreads();

    // =========================== PHASE 2: deform GEMM ======================
    if (warp >= 4) {
        // producer
        const int px = (warp - 4) * 32 + lane;
        const float* xb = x + (size_t)b * CC * HWSZ;

        float cw0, cw1, cw2, cw3;
        int   ci0, ci1, ci2, ci3;
        int s = 0;
        for (int p = 0; p < 36; p++) {
            const int tap = p >> 2;
            const int q   = p & 3;
            if (q == 0) {
                float offx = om_s[tap * 128 + px];
                float offy = om_s[(9 + tap) * 128 + px];
                float mz   = om_s[(18 + tap) * 128 + px];
                float m    = 1.f / (1.f + __expf(-mz));
                float ys = (float)(y + tap / 3 - 1) + offy;
                float xs = (float)(px + tap % 3 - 1) + offx;
                float y0f = floorf(ys), x0f = floorf(xs);
                float wy1 = ys - y0f, wx1 = xs - x0f;
                int iy0 = (int)y0f, ix0 = (int)x0f;
                bool vy0 = (iy0 >= 0) && (iy0 < HH);
                bool vy1 = (iy0 + 1 >= 0) && (iy0 + 1 < HH);
                bool vx0 = (ix0 >= 0) && (ix0 < WW);
                bool vx1 = (ix0 + 1 >= 0) && (ix0 + 1 < WW);
                cw0 = (vy0 && vx0) ? (1.f - wy1) * (1.f - wx1) * m : 0.f;
                cw1 = (vy0 && vx1) ? (1.f - wy1) * wx1 * m : 0.f;
                cw2 = (vy1 && vx0) ? wy1 * (1.f - wx1) * m : 0.f;
                cw3 = (vy1 && vx1) ? wy1 * wx1 * m : 0.f;
                int y0c = min(max(iy0, 0), HH - 1);
                int y1c = min(max(iy0 + 1, 0), HH - 1);
                int x0c = min(max(ix0, 0), WW - 1);
                int x1c = min(max(ix0 + 1, 0), WW - 1);
                ci0 = y0c * WW + x0c;  ci1 = y0c * WW + x1c;
                ci2 = y1c * WW + x0c;  ci3 = y1c * WW + x1c;
            }
            if (p >= 3) NBAR_SYNC(4 + s);

            if (q == 3 && tap < 8) {
                char* wd = smc + SM_W + ((tap + 1) & 1) * WS2_BUF;
                wslice_load(wd, wd + WS2_HALF, g_w2, OO * WPITCH,
                            tap + 1, px, OO);
                wslice_load(wd, wd + WS2_HALF, g_w2, OO * WPITCH,
                            tap + 1, px + 128, OO);
            }

            const float* xc0 = xb + (size_t)(q * 16) * HWSZ;
            char* ahp = smc + s * STG + px * 48;
            char* alp = ahp + STG_HALF;
            uint2 hp[4], lp[4];
#pragma unroll
            for (int j = 0; j < 4; j++) {
                float v[4];
#pragma unroll
                for (int qq = 0; qq < 4; qq++) {
                    const float* xc = xc0 + (size_t)(4 * j + qq) * HWSZ;
                    v[qq] = cw0 * __ldg(xc + ci0) + cw1 * __ldg(xc + ci1)
                          + cw2 * __ldg(xc + ci2) + cw3 * __ldg(xc + ci3);
                }
                split_pack(v, hp[j], lp[j]);
            }
            *(uint4*)(ahp)      = make_uint4(hp[0].x, hp[0].y, hp[1].x, hp[1].y);
            *(uint4*)(ahp + 16) = make_uint4(hp[2].x, hp[2].y, hp[3].x, hp[3].y);
            *(uint4*)(alp)      = make_uint4(lp[0].x, lp[0].y, lp[1].x, lp[1].y);
            *(uint4*)(alp + 16) = make_uint4(lp[2].x, lp[2].y, lp[3].x, lp[3].y);

            NBAR_ARRIVE(1 + s);
            if (++s == 3) s = 0;
        }
    } else {
        // consumer: 32 px x 64 o per warp
        float acc[2][8][4];
#pragma unroll
        for (int t = 0; t < 2; t++)
#pragma unroll
            for (int ob = 0; ob < 8; ob++)
#pragma unroll
                for (int i = 0; i < 4; i++) acc[t][ob][i] = 0.f;

        int s = 0;
        for (int p = 0; p < 36; p++) {
            const int tap = p >> 2;
            const int q   = p & 3;
            NBAR_SYNC(1 + s);

            const uint32_t stoff = (uint32_t)(s * STG);
            uint32_t ah[2][4], al[2][4];
            ldsm4(ah[0], aBase + stoff);
            ldsm4(ah[1], aBase + stoff + 16 * 48);
            ldsm4(al[0], aBase + stoff + STG_HALF);
            ldsm4(al[1], aBase + stoff + STG_HALF + 16 * 48);
            if (p < 33) NBAR_ARRIVE(4 + s);

            const uint32_t wb = sb + SM_W + (uint32_t)((tap & 1) * WS2_BUF);
            const uint32_t bcol = (uint32_t)(q * 32) + b_k8;
#pragma unroll
            for (int half = 0; half < 2; half++) {
                uint32_t bh[8], bl[8];
#pragma unroll
                for (int oi = 0; oi < 2; oi++) {
                    int obp = half * 2 + oi;
                    uint32_t roff = (uint32_t)(obp * 16) * WS_PITCH + b_row_off + bcol;
                    ldsm4(&bh[oi * 4], wb + roff);
                    ldsm4(&bl[oi * 4], wb + WS2_HALF + roff);
                }
#pragma unroll
                for (int t = 0; t < 2; t++)
#pragma unroll
                    for (int obl = 0; obl < 4; obl++) {
                        float* a = acc[t][half * 4 + obl];
                        mma_bf16(a, ah[t], &bh[obl * 2]);
                        mma_bf16(a, ah[t], &bl[obl * 2]);
                        mma_bf16(a, al[t], &bh[obl * 2]);
                    }
            }
            if (++s == 3) s = 0;
        }

        // epilogue: bias + relu
#pragma unroll
        for (int t = 0; t < 2; t++) {
            const int x1 = warp * 32 + t * 16 + (lane >> 2);
            const int x2 = x1 + 8;
#pragma unroll
            for (int ob = 0; ob < 8; ob++) {
                int o = ob * 8 + (lane & 3) * 2;
                float b0v = __ldg(b_def + o);
                float b1v = __ldg(b_def + o + 1);
                float* p1 = out + (((size_t)(b * OO + o) * HH + y) * WW + x1);
                float* p2 = out + (((size_t)(b * OO + o) * HH + y) * WW + x2);
                p1[0]    = fmaxf(acc[t][ob][0] + b0v, 0.f);
                p1[HWSZ] = fmaxf(acc[t][ob][1] + b1v, 0.f);
                p2[0]    = fmaxf(acc[t][ob][2] + b0v, 0.f);
                p2[HWSZ] = fmaxf(acc[t][ob][3] + b1v, 0.f);
            }
        }
    }
}

// ---------------------------------------------------------------------------
extern "C" void kernel_launch(void* const* d_in, const int* in_sizes, int n_in,
                              void* d_out, int out_size)
{
    const float* x     = (const float*)d_in[0];
    const float* feat  = (const float*)d_in[1];
    const float* w_off = (const float*)d_in[2];
    const float* b_off = (const float*)d_in[3];
    const float* w_def = (const float*)d_in[4];
    const float* b_def = (const float*)d_in[5];
    float* out = (float*)d_out;

    cudaFuncSetAttribute(fused_dcn_kernel,
                         cudaFuncAttributeMaxDynamicSharedMemorySize, F_SMEM);

    dim3 gridp(OO + NOFF, 5);
    prep_w_kernel<<<gridp, 128>>>(w_def, w_off);
    dim3 grid(HH, BB);
    fused_dcn_kernel<<<grid, 256, F_SMEM>>>(feat, x, b_off, b_def, out);
}